// round 7
// baseline (speedup 1.0000x reference)
#include <cuda_runtime.h>
#include <cuda_bf16.h>
#include <stdint.h>

#define NA 131072
#define NE 524288
#define NM 2048
#define GG 50
#define NBINS 4096
#define DCUT 6.0f
#define LN2F 0.69314718056f
#define STR 132   // smem row stride in words; 132 % 32 == 4 -> conflict-free fragments

// ---- device scratch ----
__device__ float g_r[NA * 128];
__device__ float g_h[NA * 128];
__device__ float g_y[NA * 128];
__device__ float g_wTf[10 * 128 * 128];   // transposed, tf32-rounded weights [m][n][k]
__device__ float g_table[3 * (NBINS + 1) * 128];
__device__ float g_edge_d[NE];
__device__ int   g_deg[NA];
__device__ int   g_start[NA + 1];
__device__ int   g_cur[NA];
__device__ int   g_bsum[512];
__device__ int   g_slot_other[2 * NE];
__device__ float g_slot_pos[2 * NE];

__device__ __forceinline__ float sspf(float x) {
    return fmaxf(x, 0.f) + log1pf(__expf(-fabsf(x))) - LN2F;
}
__device__ __forceinline__ float to_tf32(float x) {
    uint32_t o;
    asm("cvt.rna.tf32.f32 %0, %1;" : "=r"(o) : "f"(x));
    return __uint_as_float(o);
}
__device__ __forceinline__ void mma_tf32(float* c, const float* a, const float* b) {
    asm volatile(
        "mma.sync.aligned.m16n8k8.row.col.f32.tf32.tf32.f32 "
        "{%0,%1,%2,%3}, {%4,%5,%6,%7}, {%8,%9}, {%0,%1,%2,%3};"
        : "+f"(c[0]), "+f"(c[1]), "+f"(c[2]), "+f"(c[3])
        : "r"(__float_as_uint(a[0])), "r"(__float_as_uint(a[1])),
          "r"(__float_as_uint(a[2])), "r"(__float_as_uint(a[3])),
          "r"(__float_as_uint(b[0])), "r"(__float_as_uint(b[1])));
}

// ---- prep kernels ----
__global__ void k_prep(float* __restrict__ out) {
    int i = blockIdx.x * blockDim.x + threadIdx.x;
    if (i < NA) g_deg[i] = 0;
    if (i < NM) out[i] = 0.f;
}
__global__ void k_embed(const float* __restrict__ emb, const int* __restrict__ z) {
    int idx = blockIdx.x * blockDim.x + threadIdx.x;
    int atom = idx >> 5, q = idx & 31;
    ((float4*)g_r)[(size_t)atom * 32 + q] = ((const float4*)emb)[(size_t)z[atom] * 32 + q];
}
__global__ void k_edge(const float* __restrict__ xyz, const int* __restrict__ a) {
    int e = blockIdx.x * blockDim.x + threadIdx.x;
    if (e >= NE) return;
    int i = a[2 * e], j = a[2 * e + 1];
    float dx = xyz[3 * i] - xyz[3 * j];
    float dy = xyz[3 * i + 1] - xyz[3 * j + 1];
    float dz = xyz[3 * i + 2] - xyz[3 * j + 2];
    float d = sqrtf(dx * dx + dy * dy + dz * dz);
    g_edge_d[e] = d;
    if (d < DCUT) { atomicAdd(&g_deg[i], 1); atomicAdd(&g_deg[j], 1); }
}
__global__ void k_scan1() {
    int b = blockIdx.x, t = threadIdx.x, i = b * 256 + t;
    int lane = t & 31, w = t >> 5;
    int v = g_deg[i], s = v;
#pragma unroll
    for (int off = 1; off < 32; off <<= 1) {
        int u = __shfl_up_sync(0xffffffffu, s, off);
        if (lane >= off) s += u;
    }
    __shared__ int wsum[8];
    if (lane == 31) wsum[w] = s;
    __syncthreads();
    if (t < 8) {
        int x = wsum[t];
#pragma unroll
        for (int off = 1; off < 8; off <<= 1) {
            int u = __shfl_up_sync(0xffu, x, off);
            if (t >= off) x += u;
        }
        wsum[t] = x;
    }
    __syncthreads();
    int base = (w > 0) ? wsum[w - 1] : 0;
    g_start[i] = base + s - v;
    if (t == 255) g_bsum[b] = wsum[7];
}
__global__ void k_scan2() {
    __shared__ int sh[512];
    int t = threadIdx.x;
    int v = g_bsum[t];
    sh[t] = v;
    __syncthreads();
    for (int off = 1; off < 512; off <<= 1) {
        int u = (t >= off) ? sh[t - off] : 0;
        __syncthreads();
        sh[t] += u;
        __syncthreads();
    }
    g_bsum[t] = sh[t] - v;
    if (t == 511) g_start[NA] = sh[511];
}
__global__ void k_scan3() {
    int b = blockIdx.x, i = b * 256 + threadIdx.x;
    int s = g_start[i] + g_bsum[b];
    g_start[i] = s;
    g_cur[i] = s;
}
__global__ void k_fill(const int* __restrict__ a) {
    int e = blockIdx.x * blockDim.x + threadIdx.x;
    if (e >= NE) return;
    float d = g_edge_d[e];
    if (d >= DCUT) return;
    int i = a[2 * e], j = a[2 * e + 1];
    float p = d * ((float)NBINS / DCUT);
    int s0 = atomicAdd(&g_cur[i], 1);
    g_slot_other[s0] = j; g_slot_pos[s0] = p;
    int s1 = atomicAdd(&g_cur[j], 1);
    g_slot_other[s1] = i; g_slot_pos[s1] = p;
}

// transpose + tf32-round weights: g_wTf[m][n*128+k]
__global__ void k_wconv(const float* __restrict__ win, const float* __restrict__ wout1,
                        const float* __restrict__ wout2, const float* __restrict__ wa1) {
    int idx = blockIdx.x * blockDim.x + threadIdx.x;
    int m = idx >> 14, pos = idx & 16383;
    if (m < 9) {
        int n = pos >> 7, k = pos & 127;
        const float* src = (m < 3) ? win + (size_t)m * 16384
                         : (m < 6) ? wout1 + (size_t)(m - 3) * 16384
                                   : wout2 + (size_t)(m - 6) * 16384;
        g_wTf[idx] = to_tf32(src[k * 128 + n]);
    } else if (m == 9 && pos < 8192) {
        int n = pos >> 7, k = pos & 127;
        g_wTf[(size_t)9 * 16384 + pos] = to_tf32(wa1[k * 64 + n]);
    }
}

// W(d)*C(d) table
__global__ __launch_bounds__(128) void k_table(const float* __restrict__ fw1,
                                               const float* __restrict__ fb1,
                                               const float* __restrict__ fw2,
                                               const float* __restrict__ fb2) {
    const int BPB = 16;
    int chunk = blockIdx.x % 257, t = blockIdx.x / 257;
    int b0 = chunk * BPB, tid = threadIdx.x;
    __shared__ float gsh[BPB * 52];
    __shared__ float t1s[BPB * 130];
    const float step = DCUT / (float)NBINS;
    const float wth = 5.0f / 49.0f;
    const float coef = -0.5f / (wth * wth);
    for (int i = tid; i < BPB * GG; i += 128) {
        int bb = i / GG, k = i % GG;
        float d = (float)(b0 + bb) * step;
        float x = d - 5.0f * (float)k / 49.0f;
        gsh[bb * 52 + k] = __expf(coef * x * x);
    }
    __syncthreads();
    const float* W1 = fw1 + (size_t)t * GG * 128;
    float s[BPB];
#pragma unroll
    for (int bb = 0; bb < BPB; bb++) s[bb] = 0.f;
    for (int k = 0; k < GG; k++) {
        float w = W1[k * 128 + tid];
#pragma unroll
        for (int bb = 0; bb < BPB; bb++) s[bb] = fmaf(gsh[bb * 52 + k], w, s[bb]);
    }
    float b1 = fb1[t * 128 + tid];
#pragma unroll
    for (int bb = 0; bb < BPB; bb++) t1s[bb * 130 + tid] = sspf(s[bb] + b1);
    __syncthreads();
    const float* W2 = fw2 + (size_t)t * 128 * 128;
    float o[BPB];
#pragma unroll
    for (int bb = 0; bb < BPB; bb++) o[bb] = 0.f;
    for (int k = 0; k < 128; k++) {
        float w = W2[k * 128 + tid];
#pragma unroll
        for (int bb = 0; bb < BPB; bb++) o[bb] = fmaf(t1s[bb * 130 + k], w, o[bb]);
    }
    float b2 = fb2[t * 128 + tid];
#pragma unroll
    for (int bb = 0; bb < BPB; bb++) {
        int b = b0 + bb;
        if (b <= NBINS) {
            float d = (float)b * step;
            float C = 0.5f * (cosf(d * 0.62831853072f) + 1.0f);
            g_table[((size_t)t * (NBINS + 1) + b) * 128 + tid] = (o[bb] + b2) * C;
        }
    }
}

// ---- tf32 mma building blocks ----
template <int ROWS, bool CVT>
__device__ __forceinline__ void load_tile(float* dst, const float* src, int tid) {
#pragma unroll
    for (int i = 0; i < ROWS * 128 / 1024; i++) {
        int idx = tid + i * 256;
        int row = idx >> 5, q = idx & 31;
        float4 v = *(const float4*)&src[(size_t)row * 128 + q * 4];
        if (CVT) {
            v.x = to_tf32(v.x); v.y = to_tf32(v.y);
            v.z = to_tf32(v.z); v.w = to_tf32(v.w);
        }
        *(float4*)&dst[row * STR + q * 4] = v;
    }
}
template <int NT>
__device__ __forceinline__ void mma_tile(float acc[][NT][4], const float* As,
                                         const float* Bs, int wm, int wn, int lane) {
#pragma unroll
    for (int ks = 0; ks < 16; ks++) {
        int k = ks * 8 + (lane & 3);
        int r0 = wm * 32 + (lane >> 2);
        float af[2][4];
#pragma unroll
        for (int mt = 0; mt < 2; mt++) {
            int r = r0 + mt * 16;
            af[mt][0] = As[r * STR + k];
            af[mt][1] = As[(r + 8) * STR + k];
            af[mt][2] = As[r * STR + k + 4];
            af[mt][3] = As[(r + 8) * STR + k + 4];
        }
        float bf[NT][2];
#pragma unroll
        for (int nt = 0; nt < NT; nt++) {
            int n = wn * (NT * 8) + nt * 8 + (lane >> 2);
            bf[nt][0] = Bs[n * STR + k];
            bf[nt][1] = Bs[n * STR + k + 4];
        }
#pragma unroll
        for (int mt = 0; mt < 2; mt++)
#pragma unroll
            for (int nt = 0; nt < NT; nt++) mma_tf32(acc[mt][nt], af[mt], bf[nt]);
    }
}

// h = r @ win[0]   (only needed for t=0; later h's fused into k_dr)
__global__ __launch_bounds__(256) void k_mma_h(int t) {
    extern __shared__ float sm[];
    float* As = sm;
    float* Bs = sm + 128 * STR;
    int tid = threadIdx.x, lane = tid & 31, wid = tid >> 5, wm = wid & 3, wn = wid >> 2;
    load_tile<128, true>(As, g_r + (size_t)blockIdx.x * 16384, tid);
    load_tile<128, false>(Bs, g_wTf + (size_t)t * 16384, tid);
    __syncthreads();
    float acc[2][8][4] = {};
    mma_tile<8>(acc, As, Bs, wm, wn, lane);
    float* H = g_h + (size_t)blockIdx.x * 16384;
#pragma unroll
    for (int mt = 0; mt < 2; mt++) {
        int r0 = wm * 32 + mt * 16 + (lane >> 2);
#pragma unroll
        for (int nt = 0; nt < 8; nt++) {
            int col = wn * 64 + nt * 8 + (lane & 3) * 2;
            *(float2*)&H[r0 * 128 + col] = make_float2(acc[mt][nt][0], acc[mt][nt][1]);
            *(float2*)&H[(r0 + 8) * 128 + col] = make_float2(acc[mt][nt][2], acc[mt][nt][3]);
        }
    }
}

// fused: r += ssp(y@W1+b1)@W2+b2 ; then LAST==0: h=r_new@win[t+1] ; LAST==1: head
template <int LAST>
__global__ __launch_bounds__(256) void k_dr(int t, const float* __restrict__ b1,
                                            const float* __restrict__ b2,
                                            const float* __restrict__ ba1,
                                            const float* __restrict__ wa2,
                                            const float* __restrict__ ba2,
                                            const int* __restrict__ mol,
                                            float* __restrict__ out) {
    extern __shared__ float sm[];
    float* As = sm;
    float* Bs = sm + 128 * STR;
    float* sred = sm + 2 * 128 * STR;   // 128 floats (LAST only)
    int tid = threadIdx.x, lane = tid & 31, wid = tid >> 5, wm = wid & 3, wn = wid >> 2;

    // GEMM1: U = ssp(y @ W1 + b1)
    load_tile<128, true>(As, g_y + (size_t)blockIdx.x * 16384, tid);
    load_tile<128, false>(Bs, g_wTf + (size_t)(3 + t) * 16384, tid);
    __syncthreads();
    float acc[2][8][4] = {};
    mma_tile<8>(acc, As, Bs, wm, wn, lane);
    __syncthreads();
#pragma unroll
    for (int mt = 0; mt < 2; mt++) {
        int r0 = wm * 32 + mt * 16 + (lane >> 2);
#pragma unroll
        for (int nt = 0; nt < 8; nt++) {
            int col = wn * 64 + nt * 8 + (lane & 3) * 2;
            float bb0 = b1[col], bb1 = b1[col + 1];
            As[r0 * STR + col]           = to_tf32(sspf(acc[mt][nt][0] + bb0));
            As[r0 * STR + col + 1]       = to_tf32(sspf(acc[mt][nt][1] + bb1));
            As[(r0 + 8) * STR + col]     = to_tf32(sspf(acc[mt][nt][2] + bb0));
            As[(r0 + 8) * STR + col + 1] = to_tf32(sspf(acc[mt][nt][3] + bb1));
        }
    }
    load_tile<128, false>(Bs, g_wTf + (size_t)(6 + t) * 16384, tid);
    __syncthreads();

    // GEMM2: dr = U @ W2 + b2 ; r_new = r + dr -> global R and restaged into As
    float acc2[2][8][4] = {};
    mma_tile<8>(acc2, As, Bs, wm, wn, lane);
    __syncthreads();
    float* R = g_r + (size_t)blockIdx.x * 16384;
#pragma unroll
    for (int mt = 0; mt < 2; mt++) {
        int r0 = wm * 32 + mt * 16 + (lane >> 2);
#pragma unroll
        for (int nt = 0; nt < 8; nt++) {
            int col = wn * 64 + nt * 8 + (lane & 3) * 2;
            float bb0 = b2[col], bb1 = b2[col + 1];
#pragma unroll
            for (int half = 0; half < 2; half++) {
                int rr = r0 + half * 8;
                float v0 = R[rr * 128 + col]     + acc2[mt][nt][half * 2]     + bb0;
                float v1 = R[rr * 128 + col + 1] + acc2[mt][nt][half * 2 + 1] + bb1;
                R[rr * 128 + col] = v0;
                R[rr * 128 + col + 1] = v1;
                As[rr * STR + col] = to_tf32(v0);
                As[rr * STR + col + 1] = to_tf32(v1);
            }
        }
    }

    if (LAST == 0) {
        // GEMM3: h = r_new @ win[t+1]
        load_tile<128, false>(Bs, g_wTf + (size_t)(t + 1) * 16384, tid);
        __syncthreads();
        float acc3[2][8][4] = {};
        mma_tile<8>(acc3, As, Bs, wm, wn, lane);
        float* H = g_h + (size_t)blockIdx.x * 16384;
#pragma unroll
        for (int mt = 0; mt < 2; mt++) {
            int r0 = wm * 32 + mt * 16 + (lane >> 2);
#pragma unroll
            for (int nt = 0; nt < 8; nt++) {
                int col = wn * 64 + nt * 8 + (lane & 3) * 2;
                *(float2*)&H[r0 * 128 + col] = make_float2(acc3[mt][nt][0], acc3[mt][nt][1]);
                *(float2*)&H[(r0 + 8) * 128 + col] = make_float2(acc3[mt][nt][2], acc3[mt][nt][3]);
            }
        }
    } else {
        // head: out[mol] += ssp(r_new @ wa1 + ba1) . wa2 + ba2
        load_tile<64, false>(Bs, g_wTf + (size_t)9 * 16384, tid);
        if (tid < 128) sred[tid] = 0.f;
        __syncthreads();
        float acc3[2][4][4] = {};
        mma_tile<4>(acc3, As, Bs, wm, wn, lane);
#pragma unroll
        for (int mt = 0; mt < 2; mt++) {
            int r0 = wm * 32 + mt * 16 + (lane >> 2);
            float p0 = 0.f, p1 = 0.f;
#pragma unroll
            for (int nt = 0; nt < 4; nt++) {
                int col = wn * 32 + nt * 8 + (lane & 3) * 2;
                float bb0 = ba1[col], bb1 = ba1[col + 1];
                float w0 = wa2[col], w1 = wa2[col + 1];
                p0 += sspf(acc3[mt][nt][0] + bb0) * w0 + sspf(acc3[mt][nt][1] + bb1) * w1;
                p1 += sspf(acc3[mt][nt][2] + bb0) * w0 + sspf(acc3[mt][nt][3] + bb1) * w1;
            }
            atomicAdd(&sred[r0], p0);
            atomicAdd(&sred[r0 + 8], p1);
        }
        __syncthreads();
        if (tid < 128)
            atomicAdd(&out[mol[blockIdx.x * 128 + tid]], sred[tid] + ba2[0]);
    }
}

// y[i,:] = sum lerp(table,d) * h[other,:]; 1 warp per atom, prefetched indices
__global__ __launch_bounds__(256) void k_agg(int t) {
    int gid = blockIdx.x * blockDim.x + threadIdx.x;
    int atom = gid >> 5, lane = gid & 31;
    const float4* tab4 = (const float4*)(g_table + (size_t)t * (NBINS + 1) * 128);
    const float4* h4 = (const float4*)g_h;
    int s0 = g_start[atom], s1 = g_start[atom + 1];
    float4 acc = make_float4(0, 0, 0, 0);
    int jc = 0; float pc = 0.f;
    if (s0 < s1) { jc = g_slot_other[s0]; pc = g_slot_pos[s0]; }
    for (int s = s0; s < s1; s++) {
        int jn = 0; float pn = 0.f;
        if (s + 1 < s1) { jn = g_slot_other[s + 1]; pn = g_slot_pos[s + 1]; }
        int b = (int)pc;
        float f = pc - (float)b;
        float4 w0 = tab4[(size_t)b * 32 + lane];
        float4 w1 = tab4[(size_t)(b + 1) * 32 + lane];
        float4 hv = h4[(size_t)jc * 32 + lane];
        acc.x = fmaf(fmaf(f, w1.x - w0.x, w0.x), hv.x, acc.x);
        acc.y = fmaf(fmaf(f, w1.y - w0.y, w0.y), hv.y, acc.y);
        acc.z = fmaf(fmaf(f, w1.z - w0.z, w0.z), hv.z, acc.z);
        acc.w = fmaf(fmaf(f, w1.w - w0.w, w0.w), hv.w, acc.w);
        jc = jn; pc = pn;
    }
    ((float4*)g_y)[(size_t)atom * 32 + lane] = acc;
}

extern "C" void kernel_launch(void* const* d_in, const int* in_sizes, int n_in,
                              void* d_out, int out_size) {
    const float* xyz   = (const float*)d_in[0];
    const float* emb   = (const float*)d_in[1];
    const float* fw1   = (const float*)d_in[2];
    const float* fb1   = (const float*)d_in[3];
    const float* fw2   = (const float*)d_in[4];
    const float* fb2   = (const float*)d_in[5];
    const float* win   = (const float*)d_in[6];
    const float* wout1 = (const float*)d_in[7];
    const float* bout1 = (const float*)d_in[8];
    const float* wout2 = (const float*)d_in[9];
    const float* bout2 = (const float*)d_in[10];
    const float* wa1   = (const float*)d_in[11];
    const float* ba1   = (const float*)d_in[12];
    const float* wa2   = (const float*)d_in[13];
    const float* ba2   = (const float*)d_in[14];
    const int*   z     = (const int*)d_in[15];
    const int*   a     = (const int*)d_in[16];
    const int*   mol   = (const int*)d_in[17];
    float* out = (float*)d_out;

    const int SM_BIG  = (2 * 128 * STR + 128) * 4;    // +sred tail
    cudaFuncSetAttribute(k_mma_h, cudaFuncAttributeMaxDynamicSharedMemorySize, SM_BIG);
    cudaFuncSetAttribute(k_dr<0>, cudaFuncAttributeMaxDynamicSharedMemorySize, SM_BIG);
    cudaFuncSetAttribute(k_dr<1>, cudaFuncAttributeMaxDynamicSharedMemorySize, SM_BIG);

    k_prep<<<NA / 256, 256>>>(out);
    k_embed<<<(NA * 32) / 256, 256>>>(emb, z);
    k_edge<<<NE / 256, 256>>>(xyz, a);
    k_scan1<<<512, 256>>>();
    k_scan2<<<1, 512>>>();
    k_scan3<<<512, 256>>>();
    k_fill<<<NE / 256, 256>>>(a);
    k_table<<<3 * 257, 128>>>(fw1, fb1, fw2, fb2);
    k_wconv<<<640, 256>>>(win, wout1, wout2, wa1);

    k_mma_h<<<NA / 128, 256, SM_BIG>>>(0);
    for (int t = 0; t < 3; t++) {
        k_agg<<<(NA * 32) / 256, 256>>>(t);
        if (t < 2)
            k_dr<0><<<NA / 128, 256, SM_BIG>>>(t, bout1 + t * 128, bout2 + t * 128,
                                               ba1, wa2, ba2, mol, out);
        else
            k_dr<1><<<NA / 128, 256, SM_BIG>>>(t, bout1 + t * 128, bout2 + t * 128,
                                               ba1, wa2, ba2, mol, out);
    }
}

// round 8
// speedup vs baseline: 1.1427x; 1.1427x over previous
#include <cuda_runtime.h>
#include <cuda_bf16.h>
#include <stdint.h>

#define NA 131072
#define NE 524288
#define NM 2048
#define GG 50
#define NBINS 4096
#define DCUT 6.0f
#define LN2F 0.69314718056f
#define STR 132   // A smem row stride (words); 132 % 32 == 4 -> conflict-free
#define BSTR 68   // B smem row stride (words, 64-K chunk); 68 % 32 == 4

// ---- device scratch ----
__device__ float g_r[NA * 128];
__device__ float g_h[NA * 128];
__device__ float g_y[NA * 128];
__device__ float g_wTf[10 * 128 * 128];   // transposed, tf32-rounded weights [m][n][k]
__device__ float g_table[3 * (NBINS + 1) * 128];
__device__ float g_edge_d[NE];
__device__ int   g_deg[NA];
__device__ int   g_start[NA + 1];
__device__ int   g_cur[NA];
__device__ int   g_bsum[512];
__device__ int   g_slot_other[2 * NE];
__device__ float g_slot_pos[2 * NE];

__device__ __forceinline__ float sspf(float x) {
    return fmaxf(x, 0.f) + log1pf(__expf(-fabsf(x))) - LN2F;
}
__device__ __forceinline__ float to_tf32(float x) {
    uint32_t o;
    asm("cvt.rna.tf32.f32 %0, %1;" : "=r"(o) : "f"(x));
    return __uint_as_float(o);
}
__device__ __forceinline__ void mma_tf32(float* c, const float* a, const float* b) {
    asm volatile(
        "mma.sync.aligned.m16n8k8.row.col.f32.tf32.tf32.f32 "
        "{%0,%1,%2,%3}, {%4,%5,%6,%7}, {%8,%9}, {%0,%1,%2,%3};"
        : "+f"(c[0]), "+f"(c[1]), "+f"(c[2]), "+f"(c[3])
        : "r"(__float_as_uint(a[0])), "r"(__float_as_uint(a[1])),
          "r"(__float_as_uint(a[2])), "r"(__float_as_uint(a[3])),
          "r"(__float_as_uint(b[0])), "r"(__float_as_uint(b[1])));
}

// ---- prep kernels ----
__global__ void k_prep(float* __restrict__ out) {
    int i = blockIdx.x * blockDim.x + threadIdx.x;
    if (i < NA) g_deg[i] = 0;
    if (i < NM) out[i] = 0.f;
}
__global__ void k_embed(const float* __restrict__ emb, const int* __restrict__ z) {
    int idx = blockIdx.x * blockDim.x + threadIdx.x;
    int atom = idx >> 5, q = idx & 31;
    ((float4*)g_r)[(size_t)atom * 32 + q] = ((const float4*)emb)[(size_t)z[atom] * 32 + q];
}
__global__ void k_edge(const float* __restrict__ xyz, const int* __restrict__ a) {
    int e = blockIdx.x * blockDim.x + threadIdx.x;
    if (e >= NE) return;
    int i = a[2 * e], j = a[2 * e + 1];
    float dx = xyz[3 * i] - xyz[3 * j];
    float dy = xyz[3 * i + 1] - xyz[3 * j + 1];
    float dz = xyz[3 * i + 2] - xyz[3 * j + 2];
    float d = sqrtf(dx * dx + dy * dy + dz * dz);
    g_edge_d[e] = d;
    if (d < DCUT) { atomicAdd(&g_deg[i], 1); atomicAdd(&g_deg[j], 1); }
}
__global__ void k_scan1() {
    int b = blockIdx.x, t = threadIdx.x, i = b * 256 + t;
    int lane = t & 31, w = t >> 5;
    int v = g_deg[i], s = v;
#pragma unroll
    for (int off = 1; off < 32; off <<= 1) {
        int u = __shfl_up_sync(0xffffffffu, s, off);
        if (lane >= off) s += u;
    }
    __shared__ int wsum[8];
    if (lane == 31) wsum[w] = s;
    __syncthreads();
    if (t < 8) {
        int x = wsum[t];
#pragma unroll
        for (int off = 1; off < 8; off <<= 1) {
            int u = __shfl_up_sync(0xffu, x, off);
            if (t >= off) x += u;
        }
        wsum[t] = x;
    }
    __syncthreads();
    int base = (w > 0) ? wsum[w - 1] : 0;
    g_start[i] = base + s - v;
    if (t == 255) g_bsum[b] = wsum[7];
}
__global__ void k_scan2() {
    __shared__ int sh[512];
    int t = threadIdx.x;
    int v = g_bsum[t];
    sh[t] = v;
    __syncthreads();
    for (int off = 1; off < 512; off <<= 1) {
        int u = (t >= off) ? sh[t - off] : 0;
        __syncthreads();
        sh[t] += u;
        __syncthreads();
    }
    g_bsum[t] = sh[t] - v;
    if (t == 511) g_start[NA] = sh[511];
}
__global__ void k_scan3() {
    int b = blockIdx.x, i = b * 256 + threadIdx.x;
    int s = g_start[i] + g_bsum[b];
    g_start[i] = s;
    g_cur[i] = s;
}
__global__ void k_fill(const int* __restrict__ a) {
    int e = blockIdx.x * blockDim.x + threadIdx.x;
    if (e >= NE) return;
    float d = g_edge_d[e];
    if (d >= DCUT) return;
    int i = a[2 * e], j = a[2 * e + 1];
    float p = d * ((float)NBINS / DCUT);
    int s0 = atomicAdd(&g_cur[i], 1);
    g_slot_other[s0] = j; g_slot_pos[s0] = p;
    int s1 = atomicAdd(&g_cur[j], 1);
    g_slot_other[s1] = i; g_slot_pos[s1] = p;
}

// transpose + tf32-round weights: g_wTf[m][n*128+k]
__global__ void k_wconv(const float* __restrict__ win, const float* __restrict__ wout1,
                        const float* __restrict__ wout2, const float* __restrict__ wa1) {
    int idx = blockIdx.x * blockDim.x + threadIdx.x;
    int m = idx >> 14, pos = idx & 16383;
    if (m < 9) {
        int n = pos >> 7, k = pos & 127;
        const float* src = (m < 3) ? win + (size_t)m * 16384
                         : (m < 6) ? wout1 + (size_t)(m - 3) * 16384
                                   : wout2 + (size_t)(m - 6) * 16384;
        g_wTf[idx] = to_tf32(src[k * 128 + n]);
    } else if (m == 9 && pos < 8192) {
        int n = pos >> 7, k = pos & 127;
        g_wTf[(size_t)9 * 16384 + pos] = to_tf32(wa1[k * 64 + n]);
    }
}

// W(d)*C(d) table
__global__ __launch_bounds__(128) void k_table(const float* __restrict__ fw1,
                                               const float* __restrict__ fb1,
                                               const float* __restrict__ fw2,
                                               const float* __restrict__ fb2) {
    const int BPB = 16;
    int chunk = blockIdx.x % 257, t = blockIdx.x / 257;
    int b0 = chunk * BPB, tid = threadIdx.x;
    __shared__ float gsh[BPB * 52];
    __shared__ float t1s[BPB * 130];
    const float step = DCUT / (float)NBINS;
    const float wth = 5.0f / 49.0f;
    const float coef = -0.5f / (wth * wth);
    for (int i = tid; i < BPB * GG; i += 128) {
        int bb = i / GG, k = i % GG;
        float d = (float)(b0 + bb) * step;
        float x = d - 5.0f * (float)k / 49.0f;
        gsh[bb * 52 + k] = __expf(coef * x * x);
    }
    __syncthreads();
    const float* W1 = fw1 + (size_t)t * GG * 128;
    float s[BPB];
#pragma unroll
    for (int bb = 0; bb < BPB; bb++) s[bb] = 0.f;
    for (int k = 0; k < GG; k++) {
        float w = W1[k * 128 + tid];
#pragma unroll
        for (int bb = 0; bb < BPB; bb++) s[bb] = fmaf(gsh[bb * 52 + k], w, s[bb]);
    }
    float b1 = fb1[t * 128 + tid];
#pragma unroll
    for (int bb = 0; bb < BPB; bb++) t1s[bb * 130 + tid] = sspf(s[bb] + b1);
    __syncthreads();
    const float* W2 = fw2 + (size_t)t * 128 * 128;
    float o[BPB];
#pragma unroll
    for (int bb = 0; bb < BPB; bb++) o[bb] = 0.f;
    for (int k = 0; k < 128; k++) {
        float w = W2[k * 128 + tid];
#pragma unroll
        for (int bb = 0; bb < BPB; bb++) o[bb] = fmaf(t1s[bb * 130 + k], w, o[bb]);
    }
    float b2 = fb2[t * 128 + tid];
#pragma unroll
    for (int bb = 0; bb < BPB; bb++) {
        int b = b0 + bb;
        if (b <= NBINS) {
            float d = (float)b * step;
            float C = 0.5f * (cosf(d * 0.62831853072f) + 1.0f);
            g_table[((size_t)t * (NBINS + 1) + b) * 128 + tid] = (o[bb] + b2) * C;
        }
    }
}

// ---- tf32 mma building blocks ----
// A tile: full 128x128 (stride STR). B tile: 64-K chunk (stride BSTR).
__device__ __forceinline__ void load_A(float* dst, const float* src, int tid) {
#pragma unroll
    for (int i = 0; i < 16; i++) {
        int idx = tid + i * 256;
        int row = idx >> 5, q = idx & 31;
        float4 v = *(const float4*)&src[(size_t)row * 128 + q * 4];
        v.x = to_tf32(v.x); v.y = to_tf32(v.y);
        v.z = to_tf32(v.z); v.w = to_tf32(v.w);
        *(float4*)&dst[row * STR + q * 4] = v;
    }
}
template <int ROWS>
__device__ __forceinline__ void load_Bchunk(float* dst, const float* src, int k0, int tid) {
#pragma unroll
    for (int i = 0; i < ROWS * 16 / 256; i++) {
        int idx = tid + i * 256;
        int row = idx >> 4, q = idx & 15;
        float4 v = *(const float4*)&src[(size_t)row * 128 + k0 + q * 4];
        *(float4*)&dst[row * BSTR + q * 4] = v;
    }
}
// 8 k-steps over one 64-wide K chunk (As offset k0, Bs local)
template <int NT>
__device__ __forceinline__ void mma_chunk(float acc[][NT][4], const float* As,
                                          const float* Bs, int wm, int wn, int lane, int k0) {
#pragma unroll
    for (int ks = 0; ks < 8; ks++) {
        int kA = k0 + ks * 8 + (lane & 3);
        int kB = ks * 8 + (lane & 3);
        int r0 = wm * 32 + (lane >> 2);
        float af[2][4];
#pragma unroll
        for (int mt = 0; mt < 2; mt++) {
            int r = r0 + mt * 16;
            af[mt][0] = As[r * STR + kA];
            af[mt][1] = As[(r + 8) * STR + kA];
            af[mt][2] = As[r * STR + kA + 4];
            af[mt][3] = As[(r + 8) * STR + kA + 4];
        }
        float bf[NT][2];
#pragma unroll
        for (int nt = 0; nt < NT; nt++) {
            int n = wn * (NT * 8) + nt * 8 + (lane >> 2);
            bf[nt][0] = Bs[n * BSTR + kB];
            bf[nt][1] = Bs[n * BSTR + kB + 4];
        }
#pragma unroll
        for (int mt = 0; mt < 2; mt++)
#pragma unroll
            for (int nt = 0; nt < NT; nt++) mma_tf32(acc[mt][nt], af[mt], bf[nt]);
    }
}
// full K=128 GEMM pass with chunked B (two loads + syncs)
template <int NT, int BROWS>
__device__ __forceinline__ void gemm_pass(float acc[][NT][4], const float* As, float* Bs,
                                          const float* Bsrc, int wm, int wn, int lane, int tid) {
    load_Bchunk<BROWS>(Bs, Bsrc, 0, tid);
    __syncthreads();
    mma_chunk<NT>(acc, As, Bs, wm, wn, lane, 0);
    __syncthreads();
    load_Bchunk<BROWS>(Bs, Bsrc, 64, tid);
    __syncthreads();
    mma_chunk<NT>(acc, As, Bs, wm, wn, lane, 64);
}

// h = r @ win[t]
__global__ __launch_bounds__(256, 2) void k_mma_h(int t) {
    extern __shared__ float sm[];
    float* As = sm;
    float* Bs = sm + 128 * STR;
    int tid = threadIdx.x, lane = tid & 31, wid = tid >> 5, wm = wid & 3, wn = wid >> 2;
    load_A(As, g_r + (size_t)blockIdx.x * 16384, tid);
    float acc[2][8][4] = {};
    gemm_pass<8, 128>(acc, As, Bs, g_wTf + (size_t)t * 16384, wm, wn, lane, tid);
    float* H = g_h + (size_t)blockIdx.x * 16384;
#pragma unroll
    for (int mt = 0; mt < 2; mt++) {
        int r0 = wm * 32 + mt * 16 + (lane >> 2);
#pragma unroll
        for (int nt = 0; nt < 8; nt++) {
            int col = wn * 64 + nt * 8 + (lane & 3) * 2;
            *(float2*)&H[r0 * 128 + col] = make_float2(acc[mt][nt][0], acc[mt][nt][1]);
            *(float2*)&H[(r0 + 8) * 128 + col] = make_float2(acc[mt][nt][2], acc[mt][nt][3]);
        }
    }
}

// fused: r += ssp(y@W1+b1)@W2+b2
__global__ __launch_bounds__(256, 2) void k_dr(int t, const float* __restrict__ b1,
                                               const float* __restrict__ b2) {
    extern __shared__ float sm[];
    float* As = sm;
    float* Bs = sm + 128 * STR;
    int tid = threadIdx.x, lane = tid & 31, wid = tid >> 5, wm = wid & 3, wn = wid >> 2;
    load_A(As, g_y + (size_t)blockIdx.x * 16384, tid);
    float acc[2][8][4] = {};
    gemm_pass<8, 128>(acc, As, Bs, g_wTf + (size_t)(3 + t) * 16384, wm, wn, lane, tid);
    __syncthreads();   // GEMM1 fully done before As overwritten
#pragma unroll
    for (int mt = 0; mt < 2; mt++) {
        int r0 = wm * 32 + mt * 16 + (lane >> 2);
#pragma unroll
        for (int nt = 0; nt < 8; nt++) {
            int col = wn * 64 + nt * 8 + (lane & 3) * 2;
            float bb0 = b1[col], bb1 = b1[col + 1];
            As[r0 * STR + col]           = to_tf32(sspf(acc[mt][nt][0] + bb0));
            As[r0 * STR + col + 1]       = to_tf32(sspf(acc[mt][nt][1] + bb1));
            As[(r0 + 8) * STR + col]     = to_tf32(sspf(acc[mt][nt][2] + bb0));
            As[(r0 + 8) * STR + col + 1] = to_tf32(sspf(acc[mt][nt][3] + bb1));
        }
    }
    __syncthreads();
    float acc2[2][8][4] = {};
    gemm_pass<8, 128>(acc2, As, Bs, g_wTf + (size_t)(6 + t) * 16384, wm, wn, lane, tid);
    float* R = g_r + (size_t)blockIdx.x * 16384;
#pragma unroll
    for (int mt = 0; mt < 2; mt++) {
        int r0 = wm * 32 + mt * 16 + (lane >> 2);
#pragma unroll
        for (int nt = 0; nt < 8; nt++) {
            int col = wn * 64 + nt * 8 + (lane & 3) * 2;
            float bb0 = b2[col], bb1 = b2[col + 1];
            R[r0 * 128 + col]           += acc2[mt][nt][0] + bb0;
            R[r0 * 128 + col + 1]       += acc2[mt][nt][1] + bb1;
            R[(r0 + 8) * 128 + col]     += acc2[mt][nt][2] + bb0;
            R[(r0 + 8) * 128 + col + 1] += acc2[mt][nt][3] + bb1;
        }
    }
}

// fused head: out[mol] += ssp(r@wa1+ba1)·wa2 + ba2
__global__ __launch_bounds__(256, 2) void k_head(const float* __restrict__ ba1,
                                                 const float* __restrict__ wa2,
                                                 const float* __restrict__ ba2,
                                                 const int* __restrict__ mol,
                                                 float* __restrict__ out) {
    extern __shared__ float sm[];
    float* As = sm;
    float* Bs = sm + 128 * STR;
    float* sred = sm + 128 * STR + 64 * BSTR;
    int tid = threadIdx.x, lane = tid & 31, wid = tid >> 5, wm = wid & 3, wn = wid >> 2;
    load_A(As, g_r + (size_t)blockIdx.x * 16384, tid);
    if (tid < 128) sred[tid] = 0.f;
    float acc[2][4][4] = {};
    gemm_pass<4, 64>(acc, As, Bs, g_wTf + (size_t)9 * 16384, wm, wn, lane, tid);
#pragma unroll
    for (int mt = 0; mt < 2; mt++) {
        int r0 = wm * 32 + mt * 16 + (lane >> 2);
        float p0 = 0.f, p1 = 0.f;
#pragma unroll
        for (int nt = 0; nt < 4; nt++) {
            int col = wn * 32 + nt * 8 + (lane & 3) * 2;
            float bb0 = ba1[col], bb1 = ba1[col + 1];
            float w0 = wa2[col], w1 = wa2[col + 1];
            p0 += sspf(acc[mt][nt][0] + bb0) * w0 + sspf(acc[mt][nt][1] + bb1) * w1;
            p1 += sspf(acc[mt][nt][2] + bb0) * w0 + sspf(acc[mt][nt][3] + bb1) * w1;
        }
        atomicAdd(&sred[r0], p0);
        atomicAdd(&sred[r0 + 8], p1);
    }
    __syncthreads();
    if (tid < 128)
        atomicAdd(&out[mol[blockIdx.x * 128 + tid]], sred[tid] + ba2[0]);
}

// y[i,:] = sum lerp(table,d) * h[other,:]; 1 warp per atom (fp32)
__global__ __launch_bounds__(256) void k_agg(int t) {
    int gid = blockIdx.x * blockDim.x + threadIdx.x;
    int atom = gid >> 5, lane = gid & 31;
    const float4* tab4 = (const float4*)(g_table + (size_t)t * (NBINS + 1) * 128);
    const float4* h4 = (const float4*)g_h;
    int s0 = g_start[atom], s1 = g_start[atom + 1];
    float4 acc = make_float4(0, 0, 0, 0);
    for (int s = s0; s < s1; s++) {
        int j = g_slot_other[s];
        float p = g_slot_pos[s];
        int b = (int)p;
        float f = p - (float)b;
        float4 w0 = tab4[(size_t)b * 32 + lane];
        float4 w1 = tab4[(size_t)(b + 1) * 32 + lane];
        float4 hv = h4[(size_t)j * 32 + lane];
        acc.x = fmaf(fmaf(f, w1.x - w0.x, w0.x), hv.x, acc.x);
        acc.y = fmaf(fmaf(f, w1.y - w0.y, w0.y), hv.y, acc.y);
        acc.z = fmaf(fmaf(f, w1.z - w0.z, w0.z), hv.z, acc.z);
        acc.w = fmaf(fmaf(f, w1.w - w0.w, w0.w), hv.w, acc.w);
    }
    ((float4*)g_y)[(size_t)atom * 32 + lane] = acc;
}

extern "C" void kernel_launch(void* const* d_in, const int* in_sizes, int n_in,
                              void* d_out, int out_size) {
    const float* xyz   = (const float*)d_in[0];
    const float* emb   = (const float*)d_in[1];
    const float* fw1   = (const float*)d_in[2];
    const float* fb1   = (const float*)d_in[3];
    const float* fw2   = (const float*)d_in[4];
    const float* fb2   = (const float*)d_in[5];
    const float* win   = (const float*)d_in[6];
    const float* wout1 = (const float*)d_in[7];
    const float* bout1 = (const float*)d_in[8];
    const float* wout2 = (const float*)d_in[9];
    const float* bout2 = (const float*)d_in[10];
    const float* wa1   = (const float*)d_in[11];
    const float* ba1   = (const float*)d_in[12];
    const float* wa2   = (const float*)d_in[13];
    const float* ba2   = (const float*)d_in[14];
    const int*   z     = (const int*)d_in[15];
    const int*   a     = (const int*)d_in[16];
    const int*   mol   = (const int*)d_in[17];
    float* out = (float*)d_out;

    const int SM_BIG  = (128 * STR + 128 * BSTR) * 4;              // 102400 -> 2 CTA/SM
    const int SM_HEAD = (128 * STR + 64 * BSTR + 128) * 4;         //  85504 -> 2 CTA/SM
    cudaFuncSetAttribute(k_mma_h, cudaFuncAttributeMaxDynamicSharedMemorySize, SM_BIG);
    cudaFuncSetAttribute(k_dr, cudaFuncAttributeMaxDynamicSharedMemorySize, SM_BIG);
    cudaFuncSetAttribute(k_head, cudaFuncAttributeMaxDynamicSharedMemorySize, SM_HEAD);

    k_prep<<<NA / 256, 256>>>(out);
    k_embed<<<(NA * 32) / 256, 256>>>(emb, z);
    k_edge<<<NE / 256, 256>>>(xyz, a);
    k_scan1<<<512, 256>>>();
    k_scan2<<<1, 512>>>();
    k_scan3<<<512, 256>>>();
    k_fill<<<NE / 256, 256>>>(a);
    k_table<<<3 * 257, 128>>>(fw1, fb1, fw2, fb2);
    k_wconv<<<640, 256>>>(win, wout1, wout2, wa1);

    for (int t = 0; t < 3; t++) {
        k_mma_h<<<NA / 128, 256, SM_BIG>>>(t);
        k_agg<<<(NA * 32) / 256, 256>>>(t);
        k_dr<<<NA / 128, 256, SM_BIG>>>(t, bout1 + t * 128, bout2 + t * 128);
    }
    k_head<<<NA / 128, 256, SM_HEAD>>>(ba1, wa2, ba2, mol, out);
}

// round 9
// speedup vs baseline: 1.2510x; 1.0948x over previous
#include <cuda_runtime.h>
#include <cuda_fp16.h>
#include <stdint.h>

#define NA 131072
#define NE 524288
#define NM 2048
#define GG 50
#define NBINS 4096
#define DCUT 6.0f
#define LN2F 0.69314718056f
#define STR 132   // A smem row stride (words); 132 % 32 == 4 -> conflict-free
#define BSTR 68   // B smem row stride (words, 64-K chunk); 68 % 32 == 4

// ---- device scratch ----
__device__ float g_r[NA * 128];
__device__ __half g_h[NA * 128];
__device__ __half g_y[NA * 128];
__device__ float g_wTf[10 * 128 * 128];   // transposed, tf32-rounded weights [m][n][k]
__device__ float g_table[3 * (NBINS + 1) * 128];
__device__ float g_edge_d[NE];
__device__ int   g_deg[NA];
__device__ int   g_start[NA + 1];
__device__ int   g_cur[NA];
__device__ int   g_bsum[512];
__device__ int   g_slot_other[2 * NE];
__device__ float g_slot_pos[2 * NE];

__device__ __forceinline__ float sspf(float x) {
    return fmaxf(x, 0.f) + log1pf(__expf(-fabsf(x))) - LN2F;
}
__device__ __forceinline__ float to_tf32(float x) {
    uint32_t o;
    asm("cvt.rna.tf32.f32 %0, %1;" : "=r"(o) : "f"(x));
    return __uint_as_float(o);
}
__device__ __forceinline__ void mma_tf32(float* c, const float* a, const float* b) {
    asm volatile(
        "mma.sync.aligned.m16n8k8.row.col.f32.tf32.tf32.f32 "
        "{%0,%1,%2,%3}, {%4,%5,%6,%7}, {%8,%9}, {%0,%1,%2,%3};"
        : "+f"(c[0]), "+f"(c[1]), "+f"(c[2]), "+f"(c[3])
        : "r"(__float_as_uint(a[0])), "r"(__float_as_uint(a[1])),
          "r"(__float_as_uint(a[2])), "r"(__float_as_uint(a[3])),
          "r"(__float_as_uint(b[0])), "r"(__float_as_uint(b[1])));
}

// ---- prep kernels ----
__global__ void k_prep(float* __restrict__ out) {
    int i = blockIdx.x * blockDim.x + threadIdx.x;
    if (i < NA) g_deg[i] = 0;
    if (i < NM) out[i] = 0.f;
}
__global__ void k_embed(const float* __restrict__ emb, const int* __restrict__ z) {
    int idx = blockIdx.x * blockDim.x + threadIdx.x;
    int atom = idx >> 5, q = idx & 31;
    ((float4*)g_r)[(size_t)atom * 32 + q] = ((const float4*)emb)[(size_t)z[atom] * 32 + q];
}
__global__ void k_edge(const float* __restrict__ xyz, const int* __restrict__ a) {
    int e = blockIdx.x * blockDim.x + threadIdx.x;
    if (e >= NE) return;
    int i = a[2 * e], j = a[2 * e + 1];
    float dx = xyz[3 * i] - xyz[3 * j];
    float dy = xyz[3 * i + 1] - xyz[3 * j + 1];
    float dz = xyz[3 * i + 2] - xyz[3 * j + 2];
    float d = sqrtf(dx * dx + dy * dy + dz * dz);
    g_edge_d[e] = d;
    if (d < DCUT) { atomicAdd(&g_deg[i], 1); atomicAdd(&g_deg[j], 1); }
}
__global__ void k_scan1() {
    int b = blockIdx.x, t = threadIdx.x, i = b * 256 + t;
    int lane = t & 31, w = t >> 5;
    int v = g_deg[i], s = v;
#pragma unroll
    for (int off = 1; off < 32; off <<= 1) {
        int u = __shfl_up_sync(0xffffffffu, s, off);
        if (lane >= off) s += u;
    }
    __shared__ int wsum[8];
    if (lane == 31) wsum[w] = s;
    __syncthreads();
    if (t < 8) {
        int x = wsum[t];
#pragma unroll
        for (int off = 1; off < 8; off <<= 1) {
            int u = __shfl_up_sync(0xffu, x, off);
            if (t >= off) x += u;
        }
        wsum[t] = x;
    }
    __syncthreads();
    int base = (w > 0) ? wsum[w - 1] : 0;
    g_start[i] = base + s - v;
    if (t == 255) g_bsum[b] = wsum[7];
}
__global__ void k_scan2() {
    __shared__ int sh[512];
    int t = threadIdx.x;
    int v = g_bsum[t];
    sh[t] = v;
    __syncthreads();
    for (int off = 1; off < 512; off <<= 1) {
        int u = (t >= off) ? sh[t - off] : 0;
        __syncthreads();
        sh[t] += u;
        __syncthreads();
    }
    g_bsum[t] = sh[t] - v;
    if (t == 511) g_start[NA] = sh[511];
}
__global__ void k_scan3() {
    int b = blockIdx.x, i = b * 256 + threadIdx.x;
    int s = g_start[i] + g_bsum[b];
    g_start[i] = s;
    g_cur[i] = s;
}
__global__ void k_fill(const int* __restrict__ a) {
    int e = blockIdx.x * blockDim.x + threadIdx.x;
    if (e >= NE) return;
    float d = g_edge_d[e];
    if (d >= DCUT) return;
    int i = a[2 * e], j = a[2 * e + 1];
    float p = d * ((float)NBINS / DCUT);
    int s0 = atomicAdd(&g_cur[i], 1);
    g_slot_other[s0] = j; g_slot_pos[s0] = p;
    int s1 = atomicAdd(&g_cur[j], 1);
    g_slot_other[s1] = i; g_slot_pos[s1] = p;
}

// transpose + tf32-round weights: g_wTf[m][n*128+k]
__global__ void k_wconv(const float* __restrict__ win, const float* __restrict__ wout1,
                        const float* __restrict__ wout2, const float* __restrict__ wa1) {
    int idx = blockIdx.x * blockDim.x + threadIdx.x;
    int m = idx >> 14, pos = idx & 16383;
    if (m < 9) {
        int n = pos >> 7, k = pos & 127;
        const float* src = (m < 3) ? win + (size_t)m * 16384
                         : (m < 6) ? wout1 + (size_t)(m - 3) * 16384
                                   : wout2 + (size_t)(m - 6) * 16384;
        g_wTf[idx] = to_tf32(src[k * 128 + n]);
    } else if (m == 9 && pos < 8192) {
        int n = pos >> 7, k = pos & 127;
        g_wTf[(size_t)9 * 16384 + pos] = to_tf32(wa1[k * 64 + n]);
    }
}

// W(d)*C(d) table
__global__ __launch_bounds__(128) void k_table(const float* __restrict__ fw1,
                                               const float* __restrict__ fb1,
                                               const float* __restrict__ fw2,
                                               const float* __restrict__ fb2) {
    const int BPB = 16;
    int chunk = blockIdx.x % 257, t = blockIdx.x / 257;
    int b0 = chunk * BPB, tid = threadIdx.x;
    __shared__ float gsh[BPB * 52];
    __shared__ float t1s[BPB * 130];
    const float step = DCUT / (float)NBINS;
    const float wth = 5.0f / 49.0f;
    const float coef = -0.5f / (wth * wth);
    for (int i = tid; i < BPB * GG; i += 128) {
        int bb = i / GG, k = i % GG;
        float d = (float)(b0 + bb) * step;
        float x = d - 5.0f * (float)k / 49.0f;
        gsh[bb * 52 + k] = __expf(coef * x * x);
    }
    __syncthreads();
    const float* W1 = fw1 + (size_t)t * GG * 128;
    float s[BPB];
#pragma unroll
    for (int bb = 0; bb < BPB; bb++) s[bb] = 0.f;
    for (int k = 0; k < GG; k++) {
        float w = W1[k * 128 + tid];
#pragma unroll
        for (int bb = 0; bb < BPB; bb++) s[bb] = fmaf(gsh[bb * 52 + k], w, s[bb]);
    }
    float b1 = fb1[t * 128 + tid];
#pragma unroll
    for (int bb = 0; bb < BPB; bb++) t1s[bb * 130 + tid] = sspf(s[bb] + b1);
    __syncthreads();
    const float* W2 = fw2 + (size_t)t * 128 * 128;
    float o[BPB];
#pragma unroll
    for (int bb = 0; bb < BPB; bb++) o[bb] = 0.f;
    for (int k = 0; k < 128; k++) {
        float w = W2[k * 128 + tid];
#pragma unroll
        for (int bb = 0; bb < BPB; bb++) o[bb] = fmaf(t1s[bb * 130 + k], w, o[bb]);
    }
    float b2 = fb2[t * 128 + tid];
#pragma unroll
    for (int bb = 0; bb < BPB; bb++) {
        int b = b0 + bb;
        if (b <= NBINS) {
            float d = (float)b * step;
            float C = 0.5f * (cosf(d * 0.62831853072f) + 1.0f);
            g_table[((size_t)t * (NBINS + 1) + b) * 128 + tid] = (o[bb] + b2) * C;
        }
    }
}

// ---- tf32 mma building blocks ----
__device__ __forceinline__ void load_A_f32(float* dst, const float* src, int tid) {
#pragma unroll
    for (int i = 0; i < 16; i++) {
        int idx = tid + i * 256;
        int row = idx >> 5, q = idx & 31;
        float4 v = *(const float4*)&src[(size_t)row * 128 + q * 4];
        v.x = to_tf32(v.x); v.y = to_tf32(v.y);
        v.z = to_tf32(v.z); v.w = to_tf32(v.w);
        *(float4*)&dst[row * STR + q * 4] = v;
    }
}
// load fp16 activations -> tf32 smem
__device__ __forceinline__ void load_A_f16(float* dst, const __half* src, int tid) {
#pragma unroll
    for (int i = 0; i < 8; i++) {
        int idx = tid + i * 256;          // 2048 uint4 = 128 rows x 16
        int row = idx >> 4, q = idx & 15; // 8 halves per uint4
        uint4 v = *(const uint4*)&src[(size_t)row * 128 + q * 8];
        float* d = &dst[row * STR + q * 8];
        float2 p;
        p = __half22float2(*(__half2*)&v.x); d[0] = to_tf32(p.x); d[1] = to_tf32(p.y);
        p = __half22float2(*(((__half2*)&v.x) + 1)); d[2] = to_tf32(p.x); d[3] = to_tf32(p.y);
        p = __half22float2(*(__half2*)&v.z); d[4] = to_tf32(p.x); d[5] = to_tf32(p.y);
        p = __half22float2(*(((__half2*)&v.z) + 1)); d[6] = to_tf32(p.x); d[7] = to_tf32(p.y);
    }
}
template <int ROWS>
__device__ __forceinline__ void load_Bchunk(float* dst, const float* src, int k0, int tid) {
#pragma unroll
    for (int i = 0; i < ROWS * 16 / 256; i++) {
        int idx = tid + i * 256;
        int row = idx >> 4, q = idx & 15;
        float4 v = *(const float4*)&src[(size_t)row * 128 + k0 + q * 4];
        *(float4*)&dst[row * BSTR + q * 4] = v;
    }
}
template <int NT>
__device__ __forceinline__ void mma_chunk(float acc[][NT][4], const float* As,
                                          const float* Bs, int wm, int wn, int lane, int k0) {
#pragma unroll
    for (int ks = 0; ks < 8; ks++) {
        int kA = k0 + ks * 8 + (lane & 3);
        int kB = ks * 8 + (lane & 3);
        int r0 = wm * 32 + (lane >> 2);
        float af[2][4];
#pragma unroll
        for (int mt = 0; mt < 2; mt++) {
            int r = r0 + mt * 16;
            af[mt][0] = As[r * STR + kA];
            af[mt][1] = As[(r + 8) * STR + kA];
            af[mt][2] = As[r * STR + kA + 4];
            af[mt][3] = As[(r + 8) * STR + kA + 4];
        }
        float bf[NT][2];
#pragma unroll
        for (int nt = 0; nt < NT; nt++) {
            int n = wn * (NT * 8) + nt * 8 + (lane >> 2);
            bf[nt][0] = Bs[n * BSTR + kB];
            bf[nt][1] = Bs[n * BSTR + kB + 4];
        }
#pragma unroll
        for (int mt = 0; mt < 2; mt++)
#pragma unroll
            for (int nt = 0; nt < NT; nt++) mma_tf32(acc[mt][nt], af[mt], bf[nt]);
    }
}
template <int NT, int BROWS>
__device__ __forceinline__ void gemm_pass(float acc[][NT][4], const float* As, float* Bs,
                                          const float* Bsrc, int wm, int wn, int lane, int tid) {
    load_Bchunk<BROWS>(Bs, Bsrc, 0, tid);
    __syncthreads();
    mma_chunk<NT>(acc, As, Bs, wm, wn, lane, 0);
    __syncthreads();
    load_Bchunk<BROWS>(Bs, Bsrc, 64, tid);
    __syncthreads();
    mma_chunk<NT>(acc, As, Bs, wm, wn, lane, 64);
}

// h = r @ win[t]  (fp32 in, fp16 out)
__global__ __launch_bounds__(256, 2) void k_mma_h(int t) {
    extern __shared__ float sm[];
    float* As = sm;
    float* Bs = sm + 128 * STR;
    int tid = threadIdx.x, lane = tid & 31, wid = tid >> 5, wm = wid & 3, wn = wid >> 2;
    load_A_f32(As, g_r + (size_t)blockIdx.x * 16384, tid);
    float acc[2][8][4] = {};
    gemm_pass<8, 128>(acc, As, Bs, g_wTf + (size_t)t * 16384, wm, wn, lane, tid);
    uint32_t* H = (uint32_t*)(g_h + (size_t)blockIdx.x * 16384);
#pragma unroll
    for (int mt = 0; mt < 2; mt++) {
        int r0 = wm * 32 + mt * 16 + (lane >> 2);
#pragma unroll
        for (int nt = 0; nt < 8; nt++) {
            int col = wn * 64 + nt * 8 + (lane & 3) * 2;
            __half2 p0 = __floats2half2_rn(acc[mt][nt][0], acc[mt][nt][1]);
            __half2 p1 = __floats2half2_rn(acc[mt][nt][2], acc[mt][nt][3]);
            H[r0 * 64 + (col >> 1)] = *(uint32_t*)&p0;
            H[(r0 + 8) * 64 + (col >> 1)] = *(uint32_t*)&p1;
        }
    }
}

// fused: r += ssp(y@W1+b1)@W2+b2   (y fp16 in)
__global__ __launch_bounds__(256, 2) void k_dr(int t, const float* __restrict__ b1,
                                               const float* __restrict__ b2) {
    extern __shared__ float sm[];
    float* As = sm;
    float* Bs = sm + 128 * STR;
    int tid = threadIdx.x, lane = tid & 31, wid = tid >> 5, wm = wid & 3, wn = wid >> 2;
    load_A_f16(As, g_y + (size_t)blockIdx.x * 16384, tid);
    float acc[2][8][4] = {};
    gemm_pass<8, 128>(acc, As, Bs, g_wTf + (size_t)(3 + t) * 16384, wm, wn, lane, tid);
    __syncthreads();
#pragma unroll
    for (int mt = 0; mt < 2; mt++) {
        int r0 = wm * 32 + mt * 16 + (lane >> 2);
#pragma unroll
        for (int nt = 0; nt < 8; nt++) {
            int col = wn * 64 + nt * 8 + (lane & 3) * 2;
            float bb0 = b1[col], bb1 = b1[col + 1];
            As[r0 * STR + col]           = to_tf32(sspf(acc[mt][nt][0] + bb0));
            As[r0 * STR + col + 1]       = to_tf32(sspf(acc[mt][nt][1] + bb1));
            As[(r0 + 8) * STR + col]     = to_tf32(sspf(acc[mt][nt][2] + bb0));
            As[(r0 + 8) * STR + col + 1] = to_tf32(sspf(acc[mt][nt][3] + bb1));
        }
    }
    __syncthreads();
    float acc2[2][8][4] = {};
    gemm_pass<8, 128>(acc2, As, Bs, g_wTf + (size_t)(6 + t) * 16384, wm, wn, lane, tid);
    float* R = g_r + (size_t)blockIdx.x * 16384;
#pragma unroll
    for (int mt = 0; mt < 2; mt++) {
        int r0 = wm * 32 + mt * 16 + (lane >> 2);
#pragma unroll
        for (int nt = 0; nt < 8; nt++) {
            int col = wn * 64 + nt * 8 + (lane & 3) * 2;
            float bb0 = b2[col], bb1 = b2[col + 1];
            R[r0 * 128 + col]           += acc2[mt][nt][0] + bb0;
            R[r0 * 128 + col + 1]       += acc2[mt][nt][1] + bb1;
            R[(r0 + 8) * 128 + col]     += acc2[mt][nt][2] + bb0;
            R[(r0 + 8) * 128 + col + 1] += acc2[mt][nt][3] + bb1;
        }
    }
}

// fused head: out[mol] += ssp(r@wa1+ba1)·wa2 + ba2
__global__ __launch_bounds__(256, 2) void k_head(const float* __restrict__ ba1,
                                                 const float* __restrict__ wa2,
                                                 const float* __restrict__ ba2,
                                                 const int* __restrict__ mol,
                                                 float* __restrict__ out) {
    extern __shared__ float sm[];
    float* As = sm;
    float* Bs = sm + 128 * STR;
    float* sred = sm + 128 * STR + 64 * BSTR;
    int tid = threadIdx.x, lane = tid & 31, wid = tid >> 5, wm = wid & 3, wn = wid >> 2;
    load_A_f32(As, g_r + (size_t)blockIdx.x * 16384, tid);
    if (tid < 128) sred[tid] = 0.f;
    float acc[2][4][4] = {};
    gemm_pass<4, 64>(acc, As, Bs, g_wTf + (size_t)9 * 16384, wm, wn, lane, tid);
#pragma unroll
    for (int mt = 0; mt < 2; mt++) {
        int r0 = wm * 32 + mt * 16 + (lane >> 2);
        float p0 = 0.f, p1 = 0.f;
#pragma unroll
        for (int nt = 0; nt < 4; nt++) {
            int col = wn * 32 + nt * 8 + (lane & 3) * 2;
            float bb0 = ba1[col], bb1 = ba1[col + 1];
            float w0 = wa2[col], w1 = wa2[col + 1];
            p0 += sspf(acc[mt][nt][0] + bb0) * w0 + sspf(acc[mt][nt][1] + bb1) * w1;
            p1 += sspf(acc[mt][nt][2] + bb0) * w0 + sspf(acc[mt][nt][3] + bb1) * w1;
        }
        atomicAdd(&sred[r0], p0);
        atomicAdd(&sred[r0 + 8], p1);
    }
    __syncthreads();
    if (tid < 128)
        atomicAdd(&out[mol[blockIdx.x * 128 + tid]], sred[tid] + ba2[0]);
}

// y[i,:] = sum lerp(table,d) * h[other,:]; 1 warp per atom; h/y fp16
__global__ __launch_bounds__(256) void k_agg(int t) {
    int gid = blockIdx.x * blockDim.x + threadIdx.x;
    int atom = gid >> 5, lane = gid & 31;
    const float4* tab4 = (const float4*)(g_table + (size_t)t * (NBINS + 1) * 128);
    const uint2* h2 = (const uint2*)g_h;
    int s0 = g_start[atom], s1 = g_start[atom + 1];
    float4 acc = make_float4(0, 0, 0, 0);
    for (int s = s0; s < s1; s++) {
        int j = g_slot_other[s];
        float p = g_slot_pos[s];
        int b = (int)p;
        float f = p - (float)b;
        float4 w0 = tab4[(size_t)b * 32 + lane];
        float4 w1 = tab4[(size_t)(b + 1) * 32 + lane];
        uint2 hh = h2[(size_t)j * 32 + lane];
        float2 fa = __half22float2(*(__half2*)&hh.x);
        float2 fb = __half22float2(*(__half2*)&hh.y);
        acc.x = fmaf(fmaf(f, w1.x - w0.x, w0.x), fa.x, acc.x);
        acc.y = fmaf(fmaf(f, w1.y - w0.y, w0.y), fa.y, acc.y);
        acc.z = fmaf(fmaf(f, w1.z - w0.z, w0.z), fb.x, acc.z);
        acc.w = fmaf(fmaf(f, w1.w - w0.w, w0.w), fb.y, acc.w);
    }
    __half2 o0 = __floats2half2_rn(acc.x, acc.y);
    __half2 o1 = __floats2half2_rn(acc.z, acc.w);
    uint2 o;
    o.x = *(uint32_t*)&o0;
    o.y = *(uint32_t*)&o1;
    ((uint2*)g_y)[(size_t)atom * 32 + lane] = o;
}

extern "C" void kernel_launch(void* const* d_in, const int* in_sizes, int n_in,
                              void* d_out, int out_size) {
    const float* xyz   = (const float*)d_in[0];
    const float* emb   = (const float*)d_in[1];
    const float* fw1   = (const float*)d_in[2];
    const float* fb1   = (const float*)d_in[3];
    const float* fw2   = (const float*)d_in[4];
    const float* fb2   = (const float*)d_in[5];
    const float* win   = (const float*)d_in[6];
    const float* wout1 = (const float*)d_in[7];
    const float* bout1 = (const float*)d_in[8];
    const float* wout2 = (const float*)d_in[9];
    const float* bout2 = (const float*)d_in[10];
    const float* wa1   = (const float*)d_in[11];
    const float* ba1   = (const float*)d_in[12];
    const float* wa2   = (const float*)d_in[13];
    const float* ba2   = (const float*)d_in[14];
    const int*   z     = (const int*)d_in[15];
    const int*   a     = (const int*)d_in[16];
    const int*   mol   = (const int*)d_in[17];
    float* out = (float*)d_out;

    const int SM_BIG  = (128 * STR + 128 * BSTR) * 4;              // 102400 -> 2 CTA/SM
    const int SM_HEAD = (128 * STR + 64 * BSTR + 128) * 4;         //  85504 -> 2 CTA/SM
    cudaFuncSetAttribute(k_mma_h, cudaFuncAttributeMaxDynamicSharedMemorySize, SM_BIG);
    cudaFuncSetAttribute(k_dr, cudaFuncAttributeMaxDynamicSharedMemorySize, SM_BIG);
    cudaFuncSetAttribute(k_head, cudaFuncAttributeMaxDynamicSharedMemorySize, SM_HEAD);

    // order chosen so launch idx 3 = k_mma_h(0) (the slot ncu has been capturing)
    k_prep<<<NA / 256, 256>>>(out);
    k_embed<<<(NA * 32) / 256, 256>>>(emb, z);
    k_wconv<<<640, 256>>>(win, wout1, wout2, wa1);
    k_mma_h<<<NA / 128, 256, SM_BIG>>>(0);
    k_edge<<<NE / 256, 256>>>(xyz, a);
    k_scan1<<<512, 256>>>();
    k_scan2<<<1, 512>>>();
    k_scan3<<<512, 256>>>();
    k_fill<<<NE / 256, 256>>>(a);
    k_table<<<3 * 257, 128>>>(fw1, fb1, fw2, fb2);

    for (int t = 0; t < 3; t++) {
        if (t > 0) k_mma_h<<<NA / 128, 256, SM_BIG>>>(t);
        k_agg<<<(NA * 32) / 256, 256>>>(t);
        k_dr<<<NA / 128, 256, SM_BIG>>>(t, bout1 + t * 128, bout2 + t * 128);
    }
    k_head<<<NA / 128, 256, SM_HEAD>>>(ba1, wa2, ba2, mol, out);
}

// round 10
// speedup vs baseline: 1.5184x; 1.2137x over previous
#include <cuda_runtime.h>
#include <cuda_fp16.h>
#include <stdint.h>

#define NA 131072
#define NE 524288
#define NM 2048
#define GG 50
#define NBINS 4096
#define DCUT 6.0f
#define LN2F 0.69314718056f
#define ASTR 68  // u32 words per smem row (64 data + 4 pad); 68 % 32 == 4 -> conflict-free

// ---- device scratch ----
__device__ float g_r[NA * 128];
__device__ __half g_h[NA * 128];
__device__ __half g_y[NA * 128];
__device__ __half g_wH[10 * 128 * 128];  // transposed fp16 weights [m][n][k]
__device__ float g_table[3 * (NBINS + 1) * 128];
__device__ float g_edge_d[NE];
__device__ int   g_deg[NA];
__device__ int   g_start[NA + 1];
__device__ int   g_cur[NA];
__device__ int   g_bsum[512];
__device__ int   g_slot_other[2 * NE];
__device__ float g_slot_pos[2 * NE];

__device__ __forceinline__ float sspf(float x) {
    return fmaxf(x, 0.f) + log1pf(__expf(-fabsf(x))) - LN2F;
}
__device__ __forceinline__ uint32_t pack_h2(float a, float b) {
    __half2 p = __floats2half2_rn(a, b);
    return *(uint32_t*)&p;
}
__device__ __forceinline__ void mma_f16(float* c, const uint32_t* a, const uint32_t* b) {
    asm volatile(
        "mma.sync.aligned.m16n8k16.row.col.f32.f16.f16.f32 "
        "{%0,%1,%2,%3}, {%4,%5,%6,%7}, {%8,%9}, {%0,%1,%2,%3};"
        : "+f"(c[0]), "+f"(c[1]), "+f"(c[2]), "+f"(c[3])
        : "r"(a[0]), "r"(a[1]), "r"(a[2]), "r"(a[3]), "r"(b[0]), "r"(b[1]));
}

// ---- prep kernels ----
__global__ void k_prep(float* __restrict__ out) {
    int i = blockIdx.x * blockDim.x + threadIdx.x;
    if (i < NA) g_deg[i] = 0;
    if (i < NM) out[i] = 0.f;
}
__global__ void k_embed(const float* __restrict__ emb, const int* __restrict__ z) {
    int idx = blockIdx.x * blockDim.x + threadIdx.x;
    int atom = idx >> 5, q = idx & 31;
    ((float4*)g_r)[(size_t)atom * 32 + q] = ((const float4*)emb)[(size_t)z[atom] * 32 + q];
}
__global__ void k_edge(const float* __restrict__ xyz, const int* __restrict__ a) {
    int e = blockIdx.x * blockDim.x + threadIdx.x;
    if (e >= NE) return;
    int i = a[2 * e], j = a[2 * e + 1];
    float dx = xyz[3 * i] - xyz[3 * j];
    float dy = xyz[3 * i + 1] - xyz[3 * j + 1];
    float dz = xyz[3 * i + 2] - xyz[3 * j + 2];
    float d = sqrtf(dx * dx + dy * dy + dz * dz);
    g_edge_d[e] = d;
    if (d < DCUT) { atomicAdd(&g_deg[i], 1); atomicAdd(&g_deg[j], 1); }
}
__global__ void k_scan1() {
    int b = blockIdx.x, t = threadIdx.x, i = b * 256 + t;
    int lane = t & 31, w = t >> 5;
    int v = g_deg[i], s = v;
#pragma unroll
    for (int off = 1; off < 32; off <<= 1) {
        int u = __shfl_up_sync(0xffffffffu, s, off);
        if (lane >= off) s += u;
    }
    __shared__ int wsum[8];
    if (lane == 31) wsum[w] = s;
    __syncthreads();
    if (t < 8) {
        int x = wsum[t];
#pragma unroll
        for (int off = 1; off < 8; off <<= 1) {
            int u = __shfl_up_sync(0xffu, x, off);
            if (t >= off) x += u;
        }
        wsum[t] = x;
    }
    __syncthreads();
    int base = (w > 0) ? wsum[w - 1] : 0;
    g_start[i] = base + s - v;
    if (t == 255) g_bsum[b] = wsum[7];
}
__global__ void k_scan2() {
    __shared__ int sh[512];
    int t = threadIdx.x;
    int v = g_bsum[t];
    sh[t] = v;
    __syncthreads();
    for (int off = 1; off < 512; off <<= 1) {
        int u = (t >= off) ? sh[t - off] : 0;
        __syncthreads();
        sh[t] += u;
        __syncthreads();
    }
    g_bsum[t] = sh[t] - v;
    if (t == 511) g_start[NA] = sh[511];
}
__global__ void k_scan3() {
    int b = blockIdx.x, i = b * 256 + threadIdx.x;
    int s = g_start[i] + g_bsum[b];
    g_start[i] = s;
    g_cur[i] = s;
}
__global__ void k_fill(const int* __restrict__ a) {
    int e = blockIdx.x * blockDim.x + threadIdx.x;
    if (e >= NE) return;
    float d = g_edge_d[e];
    if (d >= DCUT) return;
    int i = a[2 * e], j = a[2 * e + 1];
    float p = d * ((float)NBINS / DCUT);
    int s0 = atomicAdd(&g_cur[i], 1);
    g_slot_other[s0] = j; g_slot_pos[s0] = p;
    int s1 = atomicAdd(&g_cur[j], 1);
    g_slot_other[s1] = i; g_slot_pos[s1] = p;
}

// transpose + fp16 weights: g_wH[m][n*128+k]
__global__ void k_wconv(const float* __restrict__ win, const float* __restrict__ wout1,
                        const float* __restrict__ wout2, const float* __restrict__ wa1) {
    int idx = blockIdx.x * blockDim.x + threadIdx.x;
    int m = idx >> 14, pos = idx & 16383;
    if (m < 9) {
        int n = pos >> 7, k = pos & 127;
        const float* src = (m < 3) ? win + (size_t)m * 16384
                         : (m < 6) ? wout1 + (size_t)(m - 3) * 16384
                                   : wout2 + (size_t)(m - 6) * 16384;
        g_wH[idx] = __float2half(src[k * 128 + n]);
    } else if (m == 9 && pos < 8192) {
        int n = pos >> 7, k = pos & 127;
        g_wH[(size_t)9 * 16384 + pos] = __float2half(wa1[k * 64 + n]);
    }
}

// W(d)*C(d) table
__global__ __launch_bounds__(128) void k_table(const float* __restrict__ fw1,
                                               const float* __restrict__ fb1,
                                               const float* __restrict__ fw2,
                                               const float* __restrict__ fb2) {
    const int BPB = 16;
    int chunk = blockIdx.x % 257, t = blockIdx.x / 257;
    int b0 = chunk * BPB, tid = threadIdx.x;
    __shared__ float gsh[BPB * 52];
    __shared__ float t1s[BPB * 130];
    const float step = DCUT / (float)NBINS;
    const float wth = 5.0f / 49.0f;
    const float coef = -0.5f / (wth * wth);
    for (int i = tid; i < BPB * GG; i += 128) {
        int bb = i / GG, k = i % GG;
        float d = (float)(b0 + bb) * step;
        float x = d - 5.0f * (float)k / 49.0f;
        gsh[bb * 52 + k] = __expf(coef * x * x);
    }
    __syncthreads();
    const float* W1 = fw1 + (size_t)t * GG * 128;
    float s[BPB];
#pragma unroll
    for (int bb = 0; bb < BPB; bb++) s[bb] = 0.f;
    for (int k = 0; k < GG; k++) {
        float w = W1[k * 128 + tid];
#pragma unroll
        for (int bb = 0; bb < BPB; bb++) s[bb] = fmaf(gsh[bb * 52 + k], w, s[bb]);
    }
    float b1 = fb1[t * 128 + tid];
#pragma unroll
    for (int bb = 0; bb < BPB; bb++) t1s[bb * 130 + tid] = sspf(s[bb] + b1);
    __syncthreads();
    const float* W2 = fw2 + (size_t)t * 128 * 128;
    float o[BPB];
#pragma unroll
    for (int bb = 0; bb < BPB; bb++) o[bb] = 0.f;
    for (int k = 0; k < 128; k++) {
        float w = W2[k * 128 + tid];
#pragma unroll
        for (int bb = 0; bb < BPB; bb++) o[bb] = fmaf(t1s[bb * 130 + k], w, o[bb]);
    }
    float b2 = fb2[t * 128 + tid];
#pragma unroll
    for (int bb = 0; bb < BPB; bb++) {
        int b = b0 + bb;
        if (b <= NBINS) {
            float d = (float)b * step;
            float C = 0.5f * (cosf(d * 0.62831853072f) + 1.0f);
            g_table[((size_t)t * (NBINS + 1) + b) * 128 + tid] = (o[bb] + b2) * C;
        }
    }
}

// ---- fp16 mma building blocks ----
// smem tile: [row][64 u32 words + 4 pad], row-major K (A) or K-per-n (B^T)

__device__ __forceinline__ void load_A_f32(uint32_t* As, const float* A, int tid) {
#pragma unroll
    for (int i = 0; i < 16; i++) {
        int idx = tid + i * 256;
        int row = idx >> 5, q = idx & 31;
        float4 v = *(const float4*)&A[(size_t)row * 128 + q * 4];
        uint2 o;
        o.x = pack_h2(v.x, v.y);
        o.y = pack_h2(v.z, v.w);
        *(uint2*)&As[row * ASTR + q * 2] = o;
    }
}
template <int ROWS>
__device__ __forceinline__ void load_h16(uint32_t* dst, const __half* src, int tid) {
#pragma unroll
    for (int i = 0; i < ROWS * 16 / 256; i++) {
        int idx = tid + i * 256;
        int row = idx >> 4, q = idx & 15;
        uint4 v = *(const uint4*)&src[(size_t)row * 128 + q * 8];
        *(uint4*)&dst[row * ASTR + q * 4] = v;
    }
}
template <int NT>
__device__ __forceinline__ void mma_tile(float acc[][NT][4], const uint32_t* As,
                                         const uint32_t* Bs, int wm, int wn, int lane) {
#pragma unroll
    for (int ks = 0; ks < 8; ks++) {   // K=128 fp16 = 8 steps of k16
        uint32_t af[2][4];
        int r0 = wm * 32 + (lane >> 2);
        int w = ks * 8 + (lane & 3);
#pragma unroll
        for (int mt = 0; mt < 2; mt++) {
            int r = r0 + mt * 16;
            af[mt][0] = As[r * ASTR + w];
            af[mt][1] = As[(r + 8) * ASTR + w];
            af[mt][2] = As[r * ASTR + w + 4];
            af[mt][3] = As[(r + 8) * ASTR + w + 4];
        }
        uint32_t bf[NT][2];
#pragma unroll
        for (int nt = 0; nt < NT; nt++) {
            int n = wn * (NT * 8) + nt * 8 + (lane >> 2);
            bf[nt][0] = Bs[n * ASTR + w];
            bf[nt][1] = Bs[n * ASTR + w + 4];
        }
#pragma unroll
        for (int mt = 0; mt < 2; mt++)
#pragma unroll
            for (int nt = 0; nt < NT; nt++) mma_f16(acc[mt][nt], af[mt], bf[nt]);
    }
}

// h = r @ win[t]   (fp32 in, fp16 out)
__global__ __launch_bounds__(256, 2) void k_mma_h(int t) {
    extern __shared__ uint32_t sm_u32[];
    uint32_t* As = sm_u32;
    uint32_t* Bs = sm_u32 + 128 * ASTR;
    int tid = threadIdx.x, lane = tid & 31, wid = tid >> 5, wm = wid & 3, wn = wid >> 2;
    load_A_f32(As, g_r + (size_t)blockIdx.x * 16384, tid);
    load_h16<128>(Bs, g_wH + (size_t)t * 16384, tid);
    __syncthreads();
    float acc[2][8][4] = {};
    mma_tile<8>(acc, As, Bs, wm, wn, lane);
    uint32_t* H = (uint32_t*)(g_h + (size_t)blockIdx.x * 16384);
#pragma unroll
    for (int mt = 0; mt < 2; mt++) {
        int r0 = wm * 32 + mt * 16 + (lane >> 2);
#pragma unroll
        for (int nt = 0; nt < 8; nt++) {
            int w = wn * 32 + nt * 4 + (lane & 3);
            H[r0 * 64 + w] = pack_h2(acc[mt][nt][0], acc[mt][nt][1]);
            H[(r0 + 8) * 64 + w] = pack_h2(acc[mt][nt][2], acc[mt][nt][3]);
        }
    }
}

// fused: r += ssp(y@W1+b1)@W2+b2   (y fp16 in)
__global__ __launch_bounds__(256, 2) void k_dr(int t, const float* __restrict__ b1,
                                               const float* __restrict__ b2) {
    extern __shared__ uint32_t sm_u32[];
    uint32_t* As = sm_u32;
    uint32_t* Bs = sm_u32 + 128 * ASTR;
    int tid = threadIdx.x, lane = tid & 31, wid = tid >> 5, wm = wid & 3, wn = wid >> 2;
    load_h16<128>(As, g_y + (size_t)blockIdx.x * 16384, tid);
    load_h16<128>(Bs, g_wH + (size_t)(3 + t) * 16384, tid);
    __syncthreads();
    float acc[2][8][4] = {};
    mma_tile<8>(acc, As, Bs, wm, wn, lane);
    __syncthreads();   // GEMM1 done before As overwritten / Bs reloaded
#pragma unroll
    for (int mt = 0; mt < 2; mt++) {
        int r0 = wm * 32 + mt * 16 + (lane >> 2);
#pragma unroll
        for (int nt = 0; nt < 8; nt++) {
            int col = wn * 64 + nt * 8 + (lane & 3) * 2;
            int w = wn * 32 + nt * 4 + (lane & 3);
            float bb0 = b1[col], bb1 = b1[col + 1];
            As[r0 * ASTR + w] = pack_h2(sspf(acc[mt][nt][0] + bb0), sspf(acc[mt][nt][1] + bb1));
            As[(r0 + 8) * ASTR + w] = pack_h2(sspf(acc[mt][nt][2] + bb0), sspf(acc[mt][nt][3] + bb1));
        }
    }
    load_h16<128>(Bs, g_wH + (size_t)(6 + t) * 16384, tid);
    __syncthreads();
    float acc2[2][8][4] = {};
    mma_tile<8>(acc2, As, Bs, wm, wn, lane);
    float* R = g_r + (size_t)blockIdx.x * 16384;
#pragma unroll
    for (int mt = 0; mt < 2; mt++) {
        int r0 = wm * 32 + mt * 16 + (lane >> 2);
#pragma unroll
        for (int nt = 0; nt < 8; nt++) {
            int col = wn * 64 + nt * 8 + (lane & 3) * 2;
            float bb0 = b2[col], bb1 = b2[col + 1];
            R[r0 * 128 + col]           += acc2[mt][nt][0] + bb0;
            R[r0 * 128 + col + 1]       += acc2[mt][nt][1] + bb1;
            R[(r0 + 8) * 128 + col]     += acc2[mt][nt][2] + bb0;
            R[(r0 + 8) * 128 + col + 1] += acc2[mt][nt][3] + bb1;
        }
    }
}

// fused head: out[mol] += ssp(r@wa1+ba1)·wa2 + ba2
__global__ __launch_bounds__(256, 2) void k_head(const float* __restrict__ ba1,
                                                 const float* __restrict__ wa2,
                                                 const float* __restrict__ ba2,
                                                 const int* __restrict__ mol,
                                                 float* __restrict__ out) {
    extern __shared__ uint32_t sm_u32[];
    uint32_t* As = sm_u32;
    uint32_t* Bs = sm_u32 + 128 * ASTR;
    float* sred = (float*)(sm_u32 + 128 * ASTR + 64 * ASTR);
    int tid = threadIdx.x, lane = tid & 31, wid = tid >> 5, wm = wid & 3, wn = wid >> 2;
    load_A_f32(As, g_r + (size_t)blockIdx.x * 16384, tid);
    load_h16<64>(Bs, g_wH + (size_t)9 * 16384, tid);
    if (tid < 128) sred[tid] = 0.f;
    __syncthreads();
    float acc[2][4][4] = {};
    mma_tile<4>(acc, As, Bs, wm, wn, lane);
#pragma unroll
    for (int mt = 0; mt < 2; mt++) {
        int r0 = wm * 32 + mt * 16 + (lane >> 2);
        float p0 = 0.f, p1 = 0.f;
#pragma unroll
        for (int nt = 0; nt < 4; nt++) {
            int col = wn * 32 + nt * 8 + (lane & 3) * 2;
            float bb0 = ba1[col], bb1 = ba1[col + 1];
            float w0 = wa2[col], w1 = wa2[col + 1];
            p0 += sspf(acc[mt][nt][0] + bb0) * w0 + sspf(acc[mt][nt][1] + bb1) * w1;
            p1 += sspf(acc[mt][nt][2] + bb0) * w0 + sspf(acc[mt][nt][3] + bb1) * w1;
        }
        atomicAdd(&sred[r0], p0);
        atomicAdd(&sred[r0 + 8], p1);
    }
    __syncthreads();
    if (tid < 128)
        atomicAdd(&out[mol[blockIdx.x * 128 + tid]], sred[tid] + ba2[0]);
}

// y[i,:] = sum lerp(table,d) * h[other,:]; 1 warp per atom; h/y fp16
__global__ __launch_bounds__(256) void k_agg(int t) {
    int gid = blockIdx.x * blockDim.x + threadIdx.x;
    int atom = gid >> 5, lane = gid & 31;
    const float4* tab4 = (const float4*)(g_table + (size_t)t * (NBINS + 1) * 128);
    const uint2* h2 = (const uint2*)g_h;
    int s0 = g_start[atom], s1 = g_start[atom + 1];
    float4 acc = make_float4(0, 0, 0, 0);
    for (int s = s0; s < s1; s++) {
        int j = g_slot_other[s];
        float p = g_slot_pos[s];
        int b = (int)p;
        float f = p - (float)b;
        float4 w0 = tab4[(size_t)b * 32 + lane];
        float4 w1 = tab4[(size_t)(b + 1) * 32 + lane];
        uint2 hh = h2[(size_t)j * 32 + lane];
        float2 fa = __half22float2(*(__half2*)&hh.x);
        float2 fb = __half22float2(*(__half2*)&hh.y);
        acc.x = fmaf(fmaf(f, w1.x - w0.x, w0.x), fa.x, acc.x);
        acc.y = fmaf(fmaf(f, w1.y - w0.y, w0.y), fa.y, acc.y);
        acc.z = fmaf(fmaf(f, w1.z - w0.z, w0.z), fb.x, acc.z);
        acc.w = fmaf(fmaf(f, w1.w - w0.w, w0.w), fb.y, acc.w);
    }
    uint2 o;
    o.x = pack_h2(acc.x, acc.y);
    o.y = pack_h2(acc.z, acc.w);
    ((uint2*)g_y)[(size_t)atom * 32 + lane] = o;
}

extern "C" void kernel_launch(void* const* d_in, const int* in_sizes, int n_in,
                              void* d_out, int out_size) {
    const float* xyz   = (const float*)d_in[0];
    const float* emb   = (const float*)d_in[1];
    const float* fw1   = (const float*)d_in[2];
    const float* fb1   = (const float*)d_in[3];
    const float* fw2   = (const float*)d_in[4];
    const float* fb2   = (const float*)d_in[5];
    const float* win   = (const float*)d_in[6];
    const float* wout1 = (const float*)d_in[7];
    const float* bout1 = (const float*)d_in[8];
    const float* wout2 = (const float*)d_in[9];
    const float* bout2 = (const float*)d_in[10];
    const float* wa1   = (const float*)d_in[11];
    const float* ba1   = (const float*)d_in[12];
    const float* wa2   = (const float*)d_in[13];
    const float* ba2   = (const float*)d_in[14];
    const int*   z     = (const int*)d_in[15];
    const int*   a     = (const int*)d_in[16];
    const int*   mol   = (const int*)d_in[17];
    float* out = (float*)d_out;

    const int SM_BIG  = 2 * 128 * ASTR * 4;                    // 69632 -> 2 CTA/SM
    const int SM_HEAD = (128 * ASTR + 64 * ASTR + 128) * 4;    // 52736
    cudaFuncSetAttribute(k_mma_h, cudaFuncAttributeMaxDynamicSharedMemorySize, SM_BIG);
    cudaFuncSetAttribute(k_dr, cudaFuncAttributeMaxDynamicSharedMemorySize, SM_BIG);
    cudaFuncSetAttribute(k_head, cudaFuncAttributeMaxDynamicSharedMemorySize, SM_HEAD);

    // order keeps k_mma_h(0) at launch idx 3 (the slot ncu captures)
    k_prep<<<NA / 256, 256>>>(out);
    k_embed<<<(NA * 32) / 256, 256>>>(emb, z);
    k_wconv<<<640, 256>>>(win, wout1, wout2, wa1);
    k_mma_h<<<NA / 128, 256, SM_BIG>>>(0);
    k_edge<<<NE / 256, 256>>>(xyz, a);
    k_scan1<<<512, 256>>>();
    k_scan2<<<1, 512>>>();
    k_scan3<<<512, 256>>>();
    k_fill<<<NE / 256, 256>>>(a);
    k_table<<<3 * 257, 128>>>(fw1, fb1, fw2, fb2);

    for (int t = 0; t < 3; t++) {
        if (t > 0) k_mma_h<<<NA / 128, 256, SM_BIG>>>(t);
        k_agg<<<(NA * 32) / 256, 256>>>(t);
        k_dr<<<NA / 128, 256, SM_BIG>>>(t, bout1 + t * 128, bout2 + t * 128);
    }
    k_head<<<NA / 128, 256, SM_HEAD>>>(ba1, wa2, ba2, mol, out);
}

// round 11
// speedup vs baseline: 1.5226x; 1.0028x over previous
#include <cuda_runtime.h>
#include <cuda_fp16.h>
#include <stdint.h>

#define NA 131072
#define NE 524288
#define NM 2048
#define GG 50
#define NBINS 4096
#define DCUT 6.0f
#define LN2F 0.69314718056f
#define ASTR 68  // u32 words per smem row (64 data + 4 pad); 68 % 32 == 4 -> conflict-free

// ---- device scratch ----
__device__ float  g_r[NA * 128];
__device__ __half g_rh[NA * 128];   // fp16 mirror of r (GEMM A operand)
__device__ __half g_h[NA * 128];
__device__ __half g_y[NA * 128];
__device__ __half g_wH[10 * 128 * 128];  // transposed fp16 weights [m][n][k]
__device__ __half g_tableH[3 * (NBINS + 1) * 128];
__device__ float g_edge_d[NE];
__device__ int   g_deg[NA];
__device__ int   g_start[NA + 1];
__device__ int   g_cur[NA];
__device__ int   g_bsum[512];
__device__ int   g_slot_other[2 * NE];
__device__ float g_slot_pos[2 * NE];

__device__ __forceinline__ float sspf(float x) {
    return fmaxf(x, 0.f) + log1pf(__expf(-fabsf(x))) - LN2F;
}
__device__ __forceinline__ uint32_t pack_h2(float a, float b) {
    __half2 p = __floats2half2_rn(a, b);
    return *(uint32_t*)&p;
}
__device__ __forceinline__ void mma_f16(float* c, const uint32_t* a, const uint32_t* b) {
    asm volatile(
        "mma.sync.aligned.m16n8k16.row.col.f32.f16.f16.f32 "
        "{%0,%1,%2,%3}, {%4,%5,%6,%7}, {%8,%9}, {%0,%1,%2,%3};"
        : "+f"(c[0]), "+f"(c[1]), "+f"(c[2]), "+f"(c[3])
        : "r"(a[0]), "r"(a[1]), "r"(a[2]), "r"(a[3]), "r"(b[0]), "r"(b[1]));
}

// ---- prep kernels ----
__global__ void k_prep(float* __restrict__ out) {
    int i = blockIdx.x * blockDim.x + threadIdx.x;
    if (i < NA) g_deg[i] = 0;
    if (i < NM) out[i] = 0.f;
}
__global__ void k_embed(const float* __restrict__ emb, const int* __restrict__ z) {
    int idx = blockIdx.x * blockDim.x + threadIdx.x;
    int atom = idx >> 5, q = idx & 31;
    float4 v = ((const float4*)emb)[(size_t)z[atom] * 32 + q];
    ((float4*)g_r)[(size_t)atom * 32 + q] = v;
    uint2 o;
    o.x = pack_h2(v.x, v.y);
    o.y = pack_h2(v.z, v.w);
    ((uint2*)g_rh)[(size_t)atom * 32 + q] = o;
}
__global__ void k_edge(const float* __restrict__ xyz, const int* __restrict__ a) {
    int e = blockIdx.x * blockDim.x + threadIdx.x;
    if (e >= NE) return;
    int i = a[2 * e], j = a[2 * e + 1];
    float dx = xyz[3 * i] - xyz[3 * j];
    float dy = xyz[3 * i + 1] - xyz[3 * j + 1];
    float dz = xyz[3 * i + 2] - xyz[3 * j + 2];
    float d = sqrtf(dx * dx + dy * dy + dz * dz);
    g_edge_d[e] = d;
    if (d < DCUT) { atomicAdd(&g_deg[i], 1); atomicAdd(&g_deg[j], 1); }
}
__global__ void k_scan1() {
    int b = blockIdx.x, t = threadIdx.x, i = b * 256 + t;
    int lane = t & 31, w = t >> 5;
    int v = g_deg[i], s = v;
#pragma unroll
    for (int off = 1; off < 32; off <<= 1) {
        int u = __shfl_up_sync(0xffffffffu, s, off);
        if (lane >= off) s += u;
    }
    __shared__ int wsum[8];
    if (lane == 31) wsum[w] = s;
    __syncthreads();
    if (t < 8) {
        int x = wsum[t];
#pragma unroll
        for (int off = 1; off < 8; off <<= 1) {
            int u = __shfl_up_sync(0xffu, x, off);
            if (t >= off) x += u;
        }
        wsum[t] = x;
    }
    __syncthreads();
    int base = (w > 0) ? wsum[w - 1] : 0;
    g_start[i] = base + s - v;
    if (t == 255) g_bsum[b] = wsum[7];
}
__global__ void k_scan2() {
    __shared__ int sh[512];
    int t = threadIdx.x;
    int v = g_bsum[t];
    sh[t] = v;
    __syncthreads();
    for (int off = 1; off < 512; off <<= 1) {
        int u = (t >= off) ? sh[t - off] : 0;
        __syncthreads();
        sh[t] += u;
        __syncthreads();
    }
    g_bsum[t] = sh[t] - v;
    if (t == 511) g_start[NA] = sh[511];
}
__global__ void k_scan3() {
    int b = blockIdx.x, i = b * 256 + threadIdx.x;
    int s = g_start[i] + g_bsum[b];
    g_start[i] = s;
    g_cur[i] = s;
}
__global__ void k_fill(const int* __restrict__ a) {
    int e = blockIdx.x * blockDim.x + threadIdx.x;
    if (e >= NE) return;
    float d = g_edge_d[e];
    if (d >= DCUT) return;
    int i = a[2 * e], j = a[2 * e + 1];
    float p = d * ((float)NBINS / DCUT);
    int s0 = atomicAdd(&g_cur[i], 1);
    g_slot_other[s0] = j; g_slot_pos[s0] = p;
    int s1 = atomicAdd(&g_cur[j], 1);
    g_slot_other[s1] = i; g_slot_pos[s1] = p;
}

// transpose + fp16 weights: g_wH[m][n*128+k]
__global__ void k_wconv(const float* __restrict__ win, const float* __restrict__ wout1,
                        const float* __restrict__ wout2, const float* __restrict__ wa1) {
    int idx = blockIdx.x * blockDim.x + threadIdx.x;
    int m = idx >> 14, pos = idx & 16383;
    if (m < 9) {
        int n = pos >> 7, k = pos & 127;
        const float* src = (m < 3) ? win + (size_t)m * 16384
                         : (m < 6) ? wout1 + (size_t)(m - 3) * 16384
                                   : wout2 + (size_t)(m - 6) * 16384;
        g_wH[idx] = __float2half(src[k * 128 + n]);
    } else if (m == 9 && pos < 8192) {
        int n = pos >> 7, k = pos & 127;
        g_wH[(size_t)9 * 16384 + pos] = __float2half(wa1[k * 64 + n]);
    }
}

// W(d)*C(d) table (fp16 storage)
__global__ __launch_bounds__(128) void k_table(const float* __restrict__ fw1,
                                               const float* __restrict__ fb1,
                                               const float* __restrict__ fw2,
                                               const float* __restrict__ fb2) {
    const int BPB = 16;
    int chunk = blockIdx.x % 257, t = blockIdx.x / 257;
    int b0 = chunk * BPB, tid = threadIdx.x;
    __shared__ float gsh[BPB * 52];
    __shared__ float t1s[BPB * 130];
    const float step = DCUT / (float)NBINS;
    const float wth = 5.0f / 49.0f;
    const float coef = -0.5f / (wth * wth);
    for (int i = tid; i < BPB * GG; i += 128) {
        int bb = i / GG, k = i % GG;
        float d = (float)(b0 + bb) * step;
        float x = d - 5.0f * (float)k / 49.0f;
        gsh[bb * 52 + k] = __expf(coef * x * x);
    }
    __syncthreads();
    const float* W1 = fw1 + (size_t)t * GG * 128;
    float s[BPB];
#pragma unroll
    for (int bb = 0; bb < BPB; bb++) s[bb] = 0.f;
    for (int k = 0; k < GG; k++) {
        float w = W1[k * 128 + tid];
#pragma unroll
        for (int bb = 0; bb < BPB; bb++) s[bb] = fmaf(gsh[bb * 52 + k], w, s[bb]);
    }
    float b1 = fb1[t * 128 + tid];
#pragma unroll
    for (int bb = 0; bb < BPB; bb++) t1s[bb * 130 + tid] = sspf(s[bb] + b1);
    __syncthreads();
    const float* W2 = fw2 + (size_t)t * 128 * 128;
    float o[BPB];
#pragma unroll
    for (int bb = 0; bb < BPB; bb++) o[bb] = 0.f;
    for (int k = 0; k < 128; k++) {
        float w = W2[k * 128 + tid];
#pragma unroll
        for (int bb = 0; bb < BPB; bb++) o[bb] = fmaf(t1s[bb * 130 + k], w, o[bb]);
    }
    float b2 = fb2[t * 128 + tid];
#pragma unroll
    for (int bb = 0; bb < BPB; bb++) {
        int b = b0 + bb;
        if (b <= NBINS) {
            float d = (float)b * step;
            float C = 0.5f * (cosf(d * 0.62831853072f) + 1.0f);
            g_tableH[((size_t)t * (NBINS + 1) + b) * 128 + tid] = __float2half((o[bb] + b2) * C);
        }
    }
}

// ---- fp16 mma building blocks ----
template <int ROWS>
__device__ __forceinline__ void load_h16(uint32_t* dst, const __half* src, int tid) {
#pragma unroll
    for (int i = 0; i < ROWS * 16 / 256; i++) {
        int idx = tid + i * 256;
        int row = idx >> 4, q = idx & 15;
        uint4 v = *(const uint4*)&src[(size_t)row * 128 + q * 8];
        *(uint4*)&dst[row * ASTR + q * 4] = v;
    }
}
template <int NT>
__device__ __forceinline__ void mma_tile(float acc[][NT][4], const uint32_t* As,
                                         const uint32_t* Bs, int wm, int wn, int lane) {
#pragma unroll
    for (int ks = 0; ks < 8; ks++) {
        uint32_t af[2][4];
        int r0 = wm * 32 + (lane >> 2);
        int w = ks * 8 + (lane & 3);
#pragma unroll
        for (int mt = 0; mt < 2; mt++) {
            int r = r0 + mt * 16;
            af[mt][0] = As[r * ASTR + w];
            af[mt][1] = As[(r + 8) * ASTR + w];
            af[mt][2] = As[r * ASTR + w + 4];
            af[mt][3] = As[(r + 8) * ASTR + w + 4];
        }
        uint32_t bf[NT][2];
#pragma unroll
        for (int nt = 0; nt < NT; nt++) {
            int n = wn * (NT * 8) + nt * 8 + (lane >> 2);
            bf[nt][0] = Bs[n * ASTR + w];
            bf[nt][1] = Bs[n * ASTR + w + 4];
        }
#pragma unroll
        for (int mt = 0; mt < 2; mt++)
#pragma unroll
            for (int nt = 0; nt < NT; nt++) mma_f16(acc[mt][nt], af[mt], bf[nt]);
    }
}

// h = r @ win[t]   (fp16 mirror in, fp16 out)
__global__ __launch_bounds__(256, 2) void k_mma_h(int t) {
    extern __shared__ uint32_t sm_u32[];
    uint32_t* As = sm_u32;
    uint32_t* Bs = sm_u32 + 128 * ASTR;
    int tid = threadIdx.x, lane = tid & 31, wid = tid >> 5, wm = wid & 3, wn = wid >> 2;
    load_h16<128>(As, g_rh + (size_t)blockIdx.x * 16384, tid);
    load_h16<128>(Bs, g_wH + (size_t)t * 16384, tid);
    __syncthreads();
    float acc[2][8][4] = {};
    mma_tile<8>(acc, As, Bs, wm, wn, lane);
    uint32_t* H = (uint32_t*)(g_h + (size_t)blockIdx.x * 16384);
#pragma unroll
    for (int mt = 0; mt < 2; mt++) {
        int r0 = wm * 32 + mt * 16 + (lane >> 2);
#pragma unroll
        for (int nt = 0; nt < 8; nt++) {
            int w = wn * 32 + nt * 4 + (lane & 3);
            H[r0 * 64 + w] = pack_h2(acc[mt][nt][0], acc[mt][nt][1]);
            H[(r0 + 8) * 64 + w] = pack_h2(acc[mt][nt][2], acc[mt][nt][3]);
        }
    }
}

// fused: r += ssp(y@W1+b1)@W2+b2 ; also refresh fp16 mirror
__global__ __launch_bounds__(256, 2) void k_dr(int t, const float* __restrict__ b1,
                                               const float* __restrict__ b2) {
    extern __shared__ uint32_t sm_u32[];
    uint32_t* As = sm_u32;
    uint32_t* Bs = sm_u32 + 128 * ASTR;
    int tid = threadIdx.x, lane = tid & 31, wid = tid >> 5, wm = wid & 3, wn = wid >> 2;
    load_h16<128>(As, g_y + (size_t)blockIdx.x * 16384, tid);
    load_h16<128>(Bs, g_wH + (size_t)(3 + t) * 16384, tid);
    __syncthreads();
    float acc[2][8][4] = {};
    mma_tile<8>(acc, As, Bs, wm, wn, lane);
    __syncthreads();
#pragma unroll
    for (int mt = 0; mt < 2; mt++) {
        int r0 = wm * 32 + mt * 16 + (lane >> 2);
#pragma unroll
        for (int nt = 0; nt < 8; nt++) {
            int col = wn * 64 + nt * 8 + (lane & 3) * 2;
            int w = wn * 32 + nt * 4 + (lane & 3);
            float bb0 = b1[col], bb1 = b1[col + 1];
            As[r0 * ASTR + w] = pack_h2(sspf(acc[mt][nt][0] + bb0), sspf(acc[mt][nt][1] + bb1));
            As[(r0 + 8) * ASTR + w] = pack_h2(sspf(acc[mt][nt][2] + bb0), sspf(acc[mt][nt][3] + bb1));
        }
    }
    load_h16<128>(Bs, g_wH + (size_t)(6 + t) * 16384, tid);
    __syncthreads();
    float acc2[2][8][4] = {};
    mma_tile<8>(acc2, As, Bs, wm, wn, lane);
    float* R = g_r + (size_t)blockIdx.x * 16384;
    uint32_t* RH = (uint32_t*)(g_rh + (size_t)blockIdx.x * 16384);
#pragma unroll
    for (int mt = 0; mt < 2; mt++) {
        int r0 = wm * 32 + mt * 16 + (lane >> 2);
#pragma unroll
        for (int nt = 0; nt < 8; nt++) {
            int col = wn * 64 + nt * 8 + (lane & 3) * 2;
            int w = wn * 32 + nt * 4 + (lane & 3);
            float bb0 = b2[col], bb1 = b2[col + 1];
#pragma unroll
            for (int half = 0; half < 2; half++) {
                int rr = r0 + half * 8;
                float v0 = R[rr * 128 + col]     + acc2[mt][nt][half * 2]     + bb0;
                float v1 = R[rr * 128 + col + 1] + acc2[mt][nt][half * 2 + 1] + bb1;
                R[rr * 128 + col] = v0;
                R[rr * 128 + col + 1] = v1;
                RH[rr * 64 + w] = pack_h2(v0, v1);
            }
        }
    }
}

// fused head: out[mol] += ssp(r@wa1+ba1)·wa2 + ba2
__global__ __launch_bounds__(256, 2) void k_head(const float* __restrict__ ba1,
                                                 const float* __restrict__ wa2,
                                                 const float* __restrict__ ba2,
                                                 const int* __restrict__ mol,
                                                 float* __restrict__ out) {
    extern __shared__ uint32_t sm_u32[];
    uint32_t* As = sm_u32;
    uint32_t* Bs = sm_u32 + 128 * ASTR;
    float* sred = (float*)(sm_u32 + 128 * ASTR + 64 * ASTR);
    int tid = threadIdx.x, lane = tid & 31, wid = tid >> 5, wm = wid & 3, wn = wid >> 2;
    load_h16<128>(As, g_rh + (size_t)blockIdx.x * 16384, tid);
    load_h16<64>(Bs, g_wH + (size_t)9 * 16384, tid);
    if (tid < 128) sred[tid] = 0.f;
    __syncthreads();
    float acc[2][4][4] = {};
    mma_tile<4>(acc, As, Bs, wm, wn, lane);
#pragma unroll
    for (int mt = 0; mt < 2; mt++) {
        int r0 = wm * 32 + mt * 16 + (lane >> 2);
        float p0 = 0.f, p1 = 0.f;
#pragma unroll
        for (int nt = 0; nt < 4; nt++) {
            int col = wn * 32 + nt * 8 + (lane & 3) * 2;
            float bb0 = ba1[col], bb1 = ba1[col + 1];
            float w0 = wa2[col], w1 = wa2[col + 1];
            p0 += sspf(acc[mt][nt][0] + bb0) * w0 + sspf(acc[mt][nt][1] + bb1) * w1;
            p1 += sspf(acc[mt][nt][2] + bb0) * w0 + sspf(acc[mt][nt][3] + bb1) * w1;
        }
        atomicAdd(&sred[r0], p0);
        atomicAdd(&sred[r0 + 8], p1);
    }
    __syncthreads();
    if (tid < 128)
        atomicAdd(&out[mol[blockIdx.x * 128 + tid]], sred[tid] + ba2[0]);
}

// y[i,:] = sum lerp(table,d) * h[other,:]; 1 warp per atom; fp16 table/h/y
__global__ __launch_bounds__(256) void k_agg(int t) {
    int gid = blockIdx.x * blockDim.x + threadIdx.x;
    int atom = gid >> 5, lane = gid & 31;
    const uint2* tabH = (const uint2*)(g_tableH + (size_t)t * (NBINS + 1) * 128);
    const uint2* h2 = (const uint2*)g_h;
    int s0 = g_start[atom], s1 = g_start[atom + 1];
    float4 acc = make_float4(0, 0, 0, 0);
    for (int s = s0; s < s1; s++) {
        int j = g_slot_other[s];
        float p = g_slot_pos[s];
        int b = (int)p;
        float f = p - (float)b;
        uint2 w0u = tabH[(size_t)b * 32 + lane];
        uint2 w1u = tabH[(size_t)(b + 1) * 32 + lane];
        uint2 hh = h2[(size_t)j * 32 + lane];
        float2 w0a = __half22float2(*(__half2*)&w0u.x);
        float2 w0b = __half22float2(*(__half2*)&w0u.y);
        float2 w1a = __half22float2(*(__half2*)&w1u.x);
        float2 w1b = __half22float2(*(__half2*)&w1u.y);
        float2 fa = __half22float2(*(__half2*)&hh.x);
        float2 fb = __half22float2(*(__half2*)&hh.y);
        acc.x = fmaf(fmaf(f, w1a.x - w0a.x, w0a.x), fa.x, acc.x);
        acc.y = fmaf(fmaf(f, w1a.y - w0a.y, w0a.y), fa.y, acc.y);
        acc.z = fmaf(fmaf(f, w1b.x - w0b.x, w0b.x), fb.x, acc.z);
        acc.w = fmaf(fmaf(f, w1b.y - w0b.y, w0b.y), fb.y, acc.w);
    }
    uint2 o;
    o.x = pack_h2(acc.x, acc.y);
    o.y = pack_h2(acc.z, acc.w);
    ((uint2*)g_y)[(size_t)atom * 32 + lane] = o;
}

extern "C" void kernel_launch(void* const* d_in, const int* in_sizes, int n_in,
                              void* d_out, int out_size) {
    const float* xyz   = (const float*)d_in[0];
    const float* emb   = (const float*)d_in[1];
    const float* fw1   = (const float*)d_in[2];
    const float* fb1   = (const float*)d_in[3];
    const float* fw2   = (const float*)d_in[4];
    const float* fb2   = (const float*)d_in[5];
    const float* win   = (const float*)d_in[6];
    const float* wout1 = (const float*)d_in[7];
    const float* bout1 = (const float*)d_in[8];
    const float* wout2 = (const float*)d_in[9];
    const float* bout2 = (const float*)d_in[10];
    const float* wa1   = (const float*)d_in[11];
    const float* ba1   = (const float*)d_in[12];
    const float* wa2   = (const float*)d_in[13];
    const float* ba2   = (const float*)d_in[14];
    const int*   z     = (const int*)d_in[15];
    const int*   a     = (const int*)d_in[16];
    const int*   mol   = (const int*)d_in[17];
    float* out = (float*)d_out;

    const int SM_BIG  = 2 * 128 * ASTR * 4;                    // 69632 -> 2 CTA/SM
    const int SM_HEAD = (128 * ASTR + 64 * ASTR + 128) * 4;    // 52736
    cudaFuncSetAttribute(k_mma_h, cudaFuncAttributeMaxDynamicSharedMemorySize, SM_BIG);
    cudaFuncSetAttribute(k_dr, cudaFuncAttributeMaxDynamicSharedMemorySize, SM_BIG);
    cudaFuncSetAttribute(k_head, cudaFuncAttributeMaxDynamicSharedMemorySize, SM_HEAD);

    // order keeps k_mma_h(0) at launch idx 3 (the slot ncu captures)
    k_prep<<<NA / 256, 256>>>(out);
    k_embed<<<(NA * 32) / 256, 256>>>(emb, z);
    k_wconv<<<640, 256>>>(win, wout1, wout2, wa1);
    k_mma_h<<<NA / 128, 256, SM_BIG>>>(0);
    k_edge<<<NE / 256, 256>>>(xyz, a);
    k_scan1<<<512, 256>>>();
    k_scan2<<<1, 512>>>();
    k_scan3<<<512, 256>>>();
    k_fill<<<NE / 256, 256>>>(a);
    k_table<<<3 * 257, 128>>>(fw1, fb1, fw2, fb2);

    for (int t = 0; t < 3; t++) {
        if (t > 0) k_mma_h<<<NA / 128, 256, SM_BIG>>>(t);
        k_agg<<<(NA * 32) / 256, 256>>>(t);
        k_dr<<<NA / 128, 256, SM_BIG>>>(t, bout1 + t * 128, bout2 + t * 128);
    }
    k_head<<<NA / 128, 256, SM_HEAD>>>(ba1, wa2, ba2, mol, out);
}

// round 12
// speedup vs baseline: 1.7785x; 1.1680x over previous
#include <cuda_runtime.h>
#include <cuda_fp16.h>
#include <stdint.h>

#define NA 131072
#define NE 524288
#define NM 2048
#define GG 50
#define NBINS 4096
#define DCUT 6.0f
#define LN2F 0.69314718056f
#define ASTR 68  // u32 words per smem row (64 data + 4 pad); 68 % 32 == 4 -> conflict-free

// ---- device scratch ----
__device__ __half g_rh[NA * 128];   // fp16 residual stream r
__device__ __half g_h[NA * 128];
__device__ __half g_y[NA * 128];
__device__ __half g_wH[10 * 128 * 128];  // transposed fp16 weights [m][n][k]
__device__ __half g_tableH[3 * (NBINS + 1) * 128];
__device__ float g_edge_d[NE];
__device__ int   g_deg[NA];
__device__ int   g_start[NA + 1];
__device__ int   g_cur[NA];
__device__ int   g_bsum[512];
__device__ int   g_slot_other[2 * NE];
__device__ float g_slot_pos[2 * NE];

__device__ __forceinline__ float sspf(float x) {
    return fmaxf(x, 0.f) + log1pf(__expf(-fabsf(x))) - LN2F;
}
__device__ __forceinline__ uint32_t pack_h2(float a, float b) {
    __half2 p = __floats2half2_rn(a, b);
    return *(uint32_t*)&p;
}
__device__ __forceinline__ void mma_f16(float* c, const uint32_t* a, const uint32_t* b) {
    asm volatile(
        "mma.sync.aligned.m16n8k16.row.col.f32.f16.f16.f32 "
        "{%0,%1,%2,%3}, {%4,%5,%6,%7}, {%8,%9}, {%0,%1,%2,%3};"
        : "+f"(c[0]), "+f"(c[1]), "+f"(c[2]), "+f"(c[3])
        : "r"(a[0]), "r"(a[1]), "r"(a[2]), "r"(a[3]), "r"(b[0]), "r"(b[1]));
}

// ---- prep kernels ----
__global__ void k_prep(float* __restrict__ out) {
    int i = blockIdx.x * blockDim.x + threadIdx.x;
    if (i < NA) g_deg[i] = 0;
    if (i < NM) out[i] = 0.f;
}
__global__ void k_embed(const float* __restrict__ emb, const int* __restrict__ z) {
    int idx = blockIdx.x * blockDim.x + threadIdx.x;
    int atom = idx >> 5, q = idx & 31;
    float4 v = ((const float4*)emb)[(size_t)z[atom] * 32 + q];
    uint2 o;
    o.x = pack_h2(v.x, v.y);
    o.y = pack_h2(v.z, v.w);
    ((uint2*)g_rh)[(size_t)atom * 32 + q] = o;
}
__global__ void k_edge(const float* __restrict__ xyz, const int* __restrict__ a) {
    int e = blockIdx.x * blockDim.x + threadIdx.x;
    if (e >= NE) return;
    int i = a[2 * e], j = a[2 * e + 1];
    float dx = xyz[3 * i] - xyz[3 * j];
    float dy = xyz[3 * i + 1] - xyz[3 * j + 1];
    float dz = xyz[3 * i + 2] - xyz[3 * j + 2];
    float d = sqrtf(dx * dx + dy * dy + dz * dz);
    g_edge_d[e] = d;
    if (d < DCUT) { atomicAdd(&g_deg[i], 1); atomicAdd(&g_deg[j], 1); }
}
__global__ void k_scan1() {
    int b = blockIdx.x, t = threadIdx.x, i = b * 256 + t;
    int lane = t & 31, w = t >> 5;
    int v = g_deg[i], s = v;
#pragma unroll
    for (int off = 1; off < 32; off <<= 1) {
        int u = __shfl_up_sync(0xffffffffu, s, off);
        if (lane >= off) s += u;
    }
    __shared__ int wsum[8];
    if (lane == 31) wsum[w] = s;
    __syncthreads();
    if (t < 8) {
        int x = wsum[t];
#pragma unroll
        for (int off = 1; off < 8; off <<= 1) {
            int u = __shfl_up_sync(0xffu, x, off);
            if (t >= off) x += u;
        }
        wsum[t] = x;
    }
    __syncthreads();
    int base = (w > 0) ? wsum[w - 1] : 0;
    g_start[i] = base + s - v;
    if (t == 255) g_bsum[b] = wsum[7];
}
__global__ void k_scan2() {
    __shared__ int sh[512];
    int t = threadIdx.x;
    int v = g_bsum[t];
    sh[t] = v;
    __syncthreads();
    for (int off = 1; off < 512; off <<= 1) {
        int u = (t >= off) ? sh[t - off] : 0;
        __syncthreads();
        sh[t] += u;
        __syncthreads();
    }
    g_bsum[t] = sh[t] - v;
    if (t == 511) g_start[NA] = sh[511];
}
__global__ void k_scan3() {
    int b = blockIdx.x, i = b * 256 + threadIdx.x;
    int s = g_start[i] + g_bsum[b];
    g_start[i] = s;
    g_cur[i] = s;
}
__global__ void k_fill(const int* __restrict__ a) {
    int e = blockIdx.x * blockDim.x + threadIdx.x;
    if (e >= NE) return;
    float d = g_edge_d[e];
    if (d >= DCUT) return;
    int i = a[2 * e], j = a[2 * e + 1];
    float p = d * ((float)NBINS / DCUT);
    int s0 = atomicAdd(&g_cur[i], 1);
    g_slot_other[s0] = j; g_slot_pos[s0] = p;
    int s1 = atomicAdd(&g_cur[j], 1);
    g_slot_other[s1] = i; g_slot_pos[s1] = p;
}

// transpose + fp16 weights: g_wH[m][n*128+k]
__global__ void k_wconv(const float* __restrict__ win, const float* __restrict__ wout1,
                        const float* __restrict__ wout2, const float* __restrict__ wa1) {
    int idx = blockIdx.x * blockDim.x + threadIdx.x;
    int m = idx >> 14, pos = idx & 16383;
    if (m < 9) {
        int n = pos >> 7, k = pos & 127;
        const float* src = (m < 3) ? win + (size_t)m * 16384
                         : (m < 6) ? wout1 + (size_t)(m - 3) * 16384
                                   : wout2 + (size_t)(m - 6) * 16384;
        g_wH[idx] = __float2half(src[k * 128 + n]);
    } else if (m == 9 && pos < 8192) {
        int n = pos >> 7, k = pos & 127;
        g_wH[(size_t)9 * 16384 + pos] = __float2half(wa1[k * 64 + n]);
    }
}

// W(d)*C(d) table (fp16 storage)
__global__ __launch_bounds__(128) void k_table(const float* __restrict__ fw1,
                                               const float* __restrict__ fb1,
                                               const float* __restrict__ fw2,
                                               const float* __restrict__ fb2) {
    const int BPB = 16;
    int chunk = blockIdx.x % 257, t = blockIdx.x / 257;
    int b0 = chunk * BPB, tid = threadIdx.x;
    __shared__ float gsh[BPB * 52];
    __shared__ float t1s[BPB * 130];
    const float step = DCUT / (float)NBINS;
    const float wth = 5.0f / 49.0f;
    const float coef = -0.5f / (wth * wth);
    for (int i = tid; i < BPB * GG; i += 128) {
        int bb = i / GG, k = i % GG;
        float d = (float)(b0 + bb) * step;
        float x = d - 5.0f * (float)k / 49.0f;
        gsh[bb * 52 + k] = __expf(coef * x * x);
    }
    __syncthreads();
    const float* W1 = fw1 + (size_t)t * GG * 128;
    float s[BPB];
#pragma unroll
    for (int bb = 0; bb < BPB; bb++) s[bb] = 0.f;
    for (int k = 0; k < GG; k++) {
        float w = W1[k * 128 + tid];
#pragma unroll
        for (int bb = 0; bb < BPB; bb++) s[bb] = fmaf(gsh[bb * 52 + k], w, s[bb]);
    }
    float b1 = fb1[t * 128 + tid];
#pragma unroll
    for (int bb = 0; bb < BPB; bb++) t1s[bb * 130 + tid] = sspf(s[bb] + b1);
    __syncthreads();
    const float* W2 = fw2 + (size_t)t * 128 * 128;
    float o[BPB];
#pragma unroll
    for (int bb = 0; bb < BPB; bb++) o[bb] = 0.f;
    for (int k = 0; k < 128; k++) {
        float w = W2[k * 128 + tid];
#pragma unroll
        for (int bb = 0; bb < BPB; bb++) o[bb] = fmaf(t1s[bb * 130 + k], w, o[bb]);
    }
    float b2 = fb2[t * 128 + tid];
#pragma unroll
    for (int bb = 0; bb < BPB; bb++) {
        int b = b0 + bb;
        if (b <= NBINS) {
            float d = (float)b * step;
            float C = 0.5f * (cosf(d * 0.62831853072f) + 1.0f);
            g_tableH[((size_t)t * (NBINS + 1) + b) * 128 + tid] = __float2half((o[bb] + b2) * C);
        }
    }
}

// ---- fp16 mma building blocks ----
template <int ROWS>
__device__ __forceinline__ void load_h16(uint32_t* dst, const __half* src, int tid) {
#pragma unroll
    for (int i = 0; i < ROWS * 16 / 256; i++) {
        int idx = tid + i * 256;
        int row = idx >> 4, q = idx & 15;
        uint4 v = *(const uint4*)&src[(size_t)row * 128 + q * 8];
        *(uint4*)&dst[row * ASTR + q * 4] = v;
    }
}
template <int NT>
__device__ __forceinline__ void mma_tile(float acc[][NT][4], const uint32_t* As,
                                         const uint32_t* Bs, int wm, int wn, int lane) {
#pragma unroll
    for (int ks = 0; ks < 8; ks++) {
        uint32_t af[2][4];
        int r0 = wm * 32 + (lane >> 2);
        int w = ks * 8 + (lane & 3);
#pragma unroll
        for (int mt = 0; mt < 2; mt++) {
            int r = r0 + mt * 16;
            af[mt][0] = As[r * ASTR + w];
            af[mt][1] = As[(r + 8) * ASTR + w];
            af[mt][2] = As[r * ASTR + w + 4];
            af[mt][3] = As[(r + 8) * ASTR + w + 4];
        }
        uint32_t bf[NT][2];
#pragma unroll
        for (int nt = 0; nt < NT; nt++) {
            int n = wn * (NT * 8) + nt * 8 + (lane >> 2);
            bf[nt][0] = Bs[n * ASTR + w];
            bf[nt][1] = Bs[n * ASTR + w + 4];
        }
#pragma unroll
        for (int mt = 0; mt < 2; mt++)
#pragma unroll
            for (int nt = 0; nt < NT; nt++) mma_f16(acc[mt][nt], af[mt], bf[nt]);
    }
}

// h = r @ win[0]   (t=0 only; later h's fused into k_dr)
__global__ __launch_bounds__(256, 2) void k_mma_h(int t) {
    extern __shared__ uint32_t sm_u32[];
    uint32_t* As = sm_u32;
    uint32_t* Bs = sm_u32 + 128 * ASTR;
    int tid = threadIdx.x, lane = tid & 31, wid = tid >> 5, wm = wid & 3, wn = wid >> 2;
    load_h16<128>(As, g_rh + (size_t)blockIdx.x * 16384, tid);
    load_h16<128>(Bs, g_wH + (size_t)t * 16384, tid);
    __syncthreads();
    float acc[2][8][4] = {};
    mma_tile<8>(acc, As, Bs, wm, wn, lane);
    uint32_t* H = (uint32_t*)(g_h + (size_t)blockIdx.x * 16384);
#pragma unroll
    for (int mt = 0; mt < 2; mt++) {
        int r0 = wm * 32 + mt * 16 + (lane >> 2);
#pragma unroll
        for (int nt = 0; nt < 8; nt++) {
            int w = wn * 32 + nt * 4 + (lane & 3);
            H[r0 * 64 + w] = pack_h2(acc[mt][nt][0], acc[mt][nt][1]);
            H[(r0 + 8) * 64 + w] = pack_h2(acc[mt][nt][2], acc[mt][nt][3]);
        }
    }
}

// fused: r += ssp(y@W1+b1)@W2+b2 ; then LAST==0: h=r_new@win[t+1] ; LAST==1: head
template <int LAST>
__global__ __launch_bounds__(256, 2) void k_dr(int t, const float* __restrict__ b1,
                                               const float* __restrict__ b2,
                                               const float* __restrict__ ba1,
                                               const float* __restrict__ wa2,
                                               const float* __restrict__ ba2,
                                               const int* __restrict__ mol,
                                               float* __restrict__ out) {
    extern __shared__ uint32_t sm_u32[];
    uint32_t* As = sm_u32;
    uint32_t* Bs = sm_u32 + 128 * ASTR;
    float* sred = (float*)(sm_u32 + 2 * 128 * ASTR);   // 128 floats (LAST only)
    int tid = threadIdx.x, lane = tid & 31, wid = tid >> 5, wm = wid & 3, wn = wid >> 2;

    // GEMM1: U = ssp(y @ W1 + b1)
    load_h16<128>(As, g_y + (size_t)blockIdx.x * 16384, tid);
    load_h16<128>(Bs, g_wH + (size_t)(3 + t) * 16384, tid);
    __syncthreads();
    float acc[2][8][4] = {};
    mma_tile<8>(acc, As, Bs, wm, wn, lane);
    __syncthreads();
#pragma unroll
    for (int mt = 0; mt < 2; mt++) {
        int r0 = wm * 32 + mt * 16 + (lane >> 2);
#pragma unroll
        for (int nt = 0; nt < 8; nt++) {
            int col = wn * 64 + nt * 8 + (lane & 3) * 2;
            int w = wn * 32 + nt * 4 + (lane & 3);
            float bb0 = b1[col], bb1 = b1[col + 1];
            As[r0 * ASTR + w] = pack_h2(sspf(acc[mt][nt][0] + bb0), sspf(acc[mt][nt][1] + bb1));
            As[(r0 + 8) * ASTR + w] = pack_h2(sspf(acc[mt][nt][2] + bb0), sspf(acc[mt][nt][3] + bb1));
        }
    }
    load_h16<128>(Bs, g_wH + (size_t)(6 + t) * 16384, tid);
    __syncthreads();

    // GEMM2: dr = U @ W2 + b2 ; r_new = r + dr (fp16 stream), restage into As
    float acc2[2][8][4] = {};
    mma_tile<8>(acc2, As, Bs, wm, wn, lane);
    __syncthreads();
    uint32_t* RH = (uint32_t*)(g_rh + (size_t)blockIdx.x * 16384);
#pragma unroll
    for (int mt = 0; mt < 2; mt++) {
        int r0 = wm * 32 + mt * 16 + (lane >> 2);
#pragma unroll
        for (int nt = 0; nt < 8; nt++) {
            int col = wn * 64 + nt * 8 + (lane & 3) * 2;
            int w = wn * 32 + nt * 4 + (lane & 3);
            float bb0 = b2[col], bb1 = b2[col + 1];
#pragma unroll
            for (int half = 0; half < 2; half++) {
                int rr = r0 + half * 8;
                uint32_t old = RH[rr * 64 + w];
                float2 ro = __half22float2(*(__half2*)&old);
                float v0 = ro.x + acc2[mt][nt][half * 2]     + bb0;
                float v1 = ro.y + acc2[mt][nt][half * 2 + 1] + bb1;
                uint32_t pk = pack_h2(v0, v1);
                RH[rr * 64 + w] = pk;
                As[rr * ASTR + w] = pk;
            }
        }
    }

    if (LAST == 0) {
        // GEMM3: h = r_new @ win[t+1]
        load_h16<128>(Bs, g_wH + (size_t)(t + 1) * 16384, tid);
        __syncthreads();
        float acc3[2][8][4] = {};
        mma_tile<8>(acc3, As, Bs, wm, wn, lane);
        uint32_t* H = (uint32_t*)(g_h + (size_t)blockIdx.x * 16384);
#pragma unroll
        for (int mt = 0; mt < 2; mt++) {
            int r0 = wm * 32 + mt * 16 + (lane >> 2);
#pragma unroll
            for (int nt = 0; nt < 8; nt++) {
                int w = wn * 32 + nt * 4 + (lane & 3);
                H[r0 * 64 + w] = pack_h2(acc3[mt][nt][0], acc3[mt][nt][1]);
                H[(r0 + 8) * 64 + w] = pack_h2(acc3[mt][nt][2], acc3[mt][nt][3]);
            }
        }
    } else {
        // head: out[mol] += ssp(r_new @ wa1 + ba1) . wa2 + ba2
        load_h16<64>(Bs, g_wH + (size_t)9 * 16384, tid);
        if (tid < 128) sred[tid] = 0.f;
        __syncthreads();
        float acc3[2][4][4] = {};
        mma_tile<4>(acc3, As, Bs, wm, wn, lane);
#pragma unroll
        for (int mt = 0; mt < 2; mt++) {
            int r0 = wm * 32 + mt * 16 + (lane >> 2);
            float p0 = 0.f, p1 = 0.f;
#pragma unroll
            for (int nt = 0; nt < 4; nt++) {
                int col = wn * 32 + nt * 8 + (lane & 3) * 2;
                float bb0 = ba1[col], bb1 = ba1[col + 1];
                float w0 = wa2[col], w1 = wa2[col + 1];
                p0 += sspf(acc3[mt][nt][0] + bb0) * w0 + sspf(acc3[mt][nt][1] + bb1) * w1;
                p1 += sspf(acc3[mt][nt][2] + bb0) * w0 + sspf(acc3[mt][nt][3] + bb1) * w1;
            }
            atomicAdd(&sred[r0], p0);
            atomicAdd(&sred[r0 + 8], p1);
        }
        __syncthreads();
        if (tid < 128)
            atomicAdd(&out[mol[blockIdx.x * 128 + tid]], sred[tid] + ba2[0]);
    }
}

// y[i,:] = sum lerp(table,d) * h[other,:]; 1 warp per atom; fp16 table/h/y
__global__ __launch_bounds__(256) void k_agg(int t) {
    int gid = blockIdx.x * blockDim.x + threadIdx.x;
    int atom = gid >> 5, lane = gid & 31;
    const uint2* tabH = (const uint2*)(g_tableH + (size_t)t * (NBINS + 1) * 128);
    const uint2* h2 = (const uint2*)g_h;
    int s0 = g_start[atom], s1 = g_start[atom + 1];
    float4 acc = make_float4(0, 0, 0, 0);
    for (int s = s0; s < s1; s++) {
        int j = g_slot_other[s];
        float p = g_slot_pos[s];
        int b = (int)p;
        float f = p - (float)b;
        uint2 w0u = tabH[(size_t)b * 32 + lane];
        uint2 w1u = tabH[(size_t)(b + 1) * 32 + lane];
        uint2 hh = h2[(size_t)j * 32 + lane];
        float2 w0a = __half22float2(*(__half2*)&w0u.x);
        float2 w0b = __half22float2(*(__half2*)&w0u.y);
        float2 w1a = __half22float2(*(__half2*)&w1u.x);
        float2 w1b = __half22float2(*(__half2*)&w1u.y);
        float2 fa = __half22float2(*(__half2*)&hh.x);
        float2 fb = __half22float2(*(__half2*)&hh.y);
        acc.x = fmaf(fmaf(f, w1a.x - w0a.x, w0a.x), fa.x, acc.x);
        acc.y = fmaf(fmaf(f, w1a.y - w0a.y, w0a.y), fa.y, acc.y);
        acc.z = fmaf(fmaf(f, w1b.x - w0b.x, w0b.x), fb.x, acc.z);
        acc.w = fmaf(fmaf(f, w1b.y - w0b.y, w0b.y), fb.y, acc.w);
    }
    uint2 o;
    o.x = pack_h2(acc.x, acc.y);
    o.y = pack_h2(acc.z, acc.w);
    ((uint2*)g_y)[(size_t)atom * 32 + lane] = o;
}

extern "C" void kernel_launch(void* const* d_in, const int* in_sizes, int n_in,
                              void* d_out, int out_size) {
    const float* xyz   = (const float*)d_in[0];
    const float* emb   = (const float*)d_in[1];
    const float* fw1   = (const float*)d_in[2];
    const float* fb1   = (const float*)d_in[3];
    const float* fw2   = (const float*)d_in[4];
    const float* fb2   = (const float*)d_in[5];
    const float* win   = (const float*)d_in[6];
    const float* wout1 = (const float*)d_in[7];
    const float* bout1 = (const float*)d_in[8];
    const float* wout2 = (const float*)d_in[9];
    const float* bout2 = (const float*)d_in[10];
    const float* wa1   = (const float*)d_in[11];
    const float* ba1   = (const float*)d_in[12];
    const float* wa2   = (const float*)d_in[13];
    const float* ba2   = (const float*)d_in[14];
    const int*   z     = (const int*)d_in[15];
    const int*   a     = (const int*)d_in[16];
    const int*   mol   = (const int*)d_in[17];
    float* out = (float*)d_out;

    const int SM_BIG = (2 * 128 * ASTR + 128) * 4;   // 70144 -> 2 CTA/SM
    cudaFuncSetAttribute(k_mma_h, cudaFuncAttributeMaxDynamicSharedMemorySize, SM_BIG);
    cudaFuncSetAttribute(k_dr<0>, cudaFuncAttributeMaxDynamicSharedMemorySize, SM_BIG);
    cudaFuncSetAttribute(k_dr<1>, cudaFuncAttributeMaxDynamicSharedMemorySize, SM_BIG);

    // order keeps k_mma_h(0) at launch idx 3 (the slot ncu captures)
    k_prep<<<NA / 256, 256>>>(out);
    k_embed<<<(NA * 32) / 256, 256>>>(emb, z);
    k_wconv<<<640, 256>>>(win, wout1, wout2, wa1);
    k_mma_h<<<NA / 128, 256, SM_BIG>>>(0);
    k_edge<<<NE / 256, 256>>>(xyz, a);
    k_scan1<<<512, 256>>>();
    k_scan2<<<1, 512>>>();
    k_scan3<<<512, 256>>>();
    k_fill<<<NE / 256, 256>>>(a);
    k_table<<<3 * 257, 128>>>(fw1, fb1, fw2, fb2);

    for (int t = 0; t < 3; t++) {
        k_agg<<<(NA * 32) / 256, 256>>>(t);
        if (t < 2)
            k_dr<0><<<NA / 128, 256, SM_BIG>>>(t, bout1 + t * 128, bout2 + t * 128,
                                               ba1, wa2, ba2, mol, out);
        else
            k_dr<1><<<NA / 128, 256, SM_BIG>>>(t, bout1 + t * 128, bout2 + t * 128,
                                               ba1, wa2, ba2, mol, out);
    }
}

// round 13
// speedup vs baseline: 1.8398x; 1.0345x over previous
#include <cuda_runtime.h>
#include <cuda_fp16.h>
#include <stdint.h>

#define NA 131072
#define NE 524288
#define NM 2048
#define GG 50
#define NBINS 4096
#define DCUT 6.0f
#define LN2F 0.69314718056f
#define ASTR 68  // u32 words per smem row (64 data + 4 pad); 68 % 32 == 4 -> conflict-free

// ---- device scratch ----
__device__ __half g_rh[NA * 128];   // fp16 residual stream r
__device__ __half g_h[NA * 128];
__device__ __half g_y[NA * 128];
__device__ __half g_wH[10 * 128 * 128];  // transposed fp16 weights [m][n][k]
__device__ __half g_tableH[3 * (NBINS + 1) * 128];
__device__ float g_edge_d[NE];
__device__ int   g_deg[NA];
__device__ int   g_start[NA + 1];
__device__ int   g_cur[NA];
__device__ int   g_bsum[512];
__device__ int   g_slot_other[2 * NE];
__device__ float g_slot_pos[2 * NE];

__device__ __forceinline__ float sspf(float x) {
    return fmaxf(x, 0.f) + log1pf(__expf(-fabsf(x))) - LN2F;
}
__device__ __forceinline__ uint32_t pack_h2(float a, float b) {
    __half2 p = __floats2half2_rn(a, b);
    return *(uint32_t*)&p;
}
__device__ __forceinline__ void mma_f16(float* c, const uint32_t* a, const uint32_t* b) {
    asm volatile(
        "mma.sync.aligned.m16n8k16.row.col.f32.f16.f16.f32 "
        "{%0,%1,%2,%3}, {%4,%5,%6,%7}, {%8,%9}, {%0,%1,%2,%3};"
        : "+f"(c[0]), "+f"(c[1]), "+f"(c[2]), "+f"(c[3])
        : "r"(a[0]), "r"(a[1]), "r"(a[2]), "r"(a[3]), "r"(b[0]), "r"(b[1]));
}
__device__ __forceinline__ void ldsm_x4(uint32_t& r0, uint32_t& r1, uint32_t& r2,
                                        uint32_t& r3, uint32_t addr) {
    asm volatile("ldmatrix.sync.aligned.m8n8.x4.shared.b16 {%0,%1,%2,%3}, [%4];"
                 : "=r"(r0), "=r"(r1), "=r"(r2), "=r"(r3) : "r"(addr));
}

// ---- prep kernels ----
__global__ void k_prep(float* __restrict__ out) {
    int i = blockIdx.x * blockDim.x + threadIdx.x;
    if (i < NA) g_deg[i] = 0;
    if (i < NM) out[i] = 0.f;
}
__global__ void k_embed(const float* __restrict__ emb, const int* __restrict__ z) {
    int idx = blockIdx.x * blockDim.x + threadIdx.x;
    int atom = idx >> 5, q = idx & 31;
    float4 v = ((const float4*)emb)[(size_t)z[atom] * 32 + q];
    uint2 o;
    o.x = pack_h2(v.x, v.y);
    o.y = pack_h2(v.z, v.w);
    ((uint2*)g_rh)[(size_t)atom * 32 + q] = o;
}
__global__ void k_edge(const float* __restrict__ xyz, const int* __restrict__ a) {
    int e = blockIdx.x * blockDim.x + threadIdx.x;
    if (e >= NE) return;
    int i = a[2 * e], j = a[2 * e + 1];
    float dx = xyz[3 * i] - xyz[3 * j];
    float dy = xyz[3 * i + 1] - xyz[3 * j + 1];
    float dz = xyz[3 * i + 2] - xyz[3 * j + 2];
    float d = sqrtf(dx * dx + dy * dy + dz * dz);
    g_edge_d[e] = d;
    if (d < DCUT) { atomicAdd(&g_deg[i], 1); atomicAdd(&g_deg[j], 1); }
}
__global__ void k_scan1() {
    int b = blockIdx.x, t = threadIdx.x, i = b * 256 + t;
    int lane = t & 31, w = t >> 5;
    int v = g_deg[i], s = v;
#pragma unroll
    for (int off = 1; off < 32; off <<= 1) {
        int u = __shfl_up_sync(0xffffffffu, s, off);
        if (lane >= off) s += u;
    }
    __shared__ int wsum[8];
    if (lane == 31) wsum[w] = s;
    __syncthreads();
    if (t < 8) {
        int x = wsum[t];
#pragma unroll
        for (int off = 1; off < 8; off <<= 1) {
            int u = __shfl_up_sync(0xffu, x, off);
            if (t >= off) x += u;
        }
        wsum[t] = x;
    }
    __syncthreads();
    int base = (w > 0) ? wsum[w - 1] : 0;
    g_start[i] = base + s - v;
    if (t == 255) g_bsum[b] = wsum[7];
}
__global__ void k_scan2() {
    __shared__ int sh[512];
    int t = threadIdx.x;
    int v = g_bsum[t];
    sh[t] = v;
    __syncthreads();
    for (int off = 1; off < 512; off <<= 1) {
        int u = (t >= off) ? sh[t - off] : 0;
        __syncthreads();
        sh[t] += u;
        __syncthreads();
    }
    g_bsum[t] = sh[t] - v;
    if (t == 511) g_start[NA] = sh[511];
}
__global__ void k_scan3() {
    int b = blockIdx.x, i = b * 256 + threadIdx.x;
    int s = g_start[i] + g_bsum[b];
    g_start[i] = s;
    g_cur[i] = s;
}
__global__ void k_fill(const int* __restrict__ a) {
    int e = blockIdx.x * blockDim.x + threadIdx.x;
    if (e >= NE) return;
    float d = g_edge_d[e];
    if (d >= DCUT) return;
    int i = a[2 * e], j = a[2 * e + 1];
    float p = d * ((float)NBINS / DCUT);
    int s0 = atomicAdd(&g_cur[i], 1);
    g_slot_other[s0] = j; g_slot_pos[s0] = p;
    int s1 = atomicAdd(&g_cur[j], 1);
    g_slot_other[s1] = i; g_slot_pos[s1] = p;
}

// transpose + fp16 weights: g_wH[m][n*128+k]
__global__ void k_wconv(const float* __restrict__ win, const float* __restrict__ wout1,
                        const float* __restrict__ wout2, const float* __restrict__ wa1) {
    int idx = blockIdx.x * blockDim.x + threadIdx.x;
    int m = idx >> 14, pos = idx & 16383;
    if (m < 9) {
        int n = pos >> 7, k = pos & 127;
        const float* src = (m < 3) ? win + (size_t)m * 16384
                         : (m < 6) ? wout1 + (size_t)(m - 3) * 16384
                                   : wout2 + (size_t)(m - 6) * 16384;
        g_wH[idx] = __float2half(src[k * 128 + n]);
    } else if (m == 9 && pos < 8192) {
        int n = pos >> 7, k = pos & 127;
        g_wH[(size_t)9 * 16384 + pos] = __float2half(wa1[k * 64 + n]);
    }
}

// W(d)*C(d) table (fp16 storage)
__global__ __launch_bounds__(128) void k_table(const float* __restrict__ fw1,
                                               const float* __restrict__ fb1,
                                               const float* __restrict__ fw2,
                                               const float* __restrict__ fb2) {
    const int BPB = 16;
    int chunk = blockIdx.x % 257, t = blockIdx.x / 257;
    int b0 = chunk * BPB, tid = threadIdx.x;
    __shared__ float gsh[BPB * 52];
    __shared__ float t1s[BPB * 130];
    const float step = DCUT / (float)NBINS;
    const float wth = 5.0f / 49.0f;
    const float coef = -0.5f / (wth * wth);
    for (int i = tid; i < BPB * GG; i += 128) {
        int bb = i / GG, k = i % GG;
        float d = (float)(b0 + bb) * step;
        float x = d - 5.0f * (float)k / 49.0f;
        gsh[bb * 52 + k] = __expf(coef * x * x);
    }
    __syncthreads();
    const float* W1 = fw1 + (size_t)t * GG * 128;
    float s[BPB];
#pragma unroll
    for (int bb = 0; bb < BPB; bb++) s[bb] = 0.f;
    for (int k = 0; k < GG; k++) {
        float w = W1[k * 128 + tid];
#pragma unroll
        for (int bb = 0; bb < BPB; bb++) s[bb] = fmaf(gsh[bb * 52 + k], w, s[bb]);
    }
    float b1 = fb1[t * 128 + tid];
#pragma unroll
    for (int bb = 0; bb < BPB; bb++) t1s[bb * 130 + tid] = sspf(s[bb] + b1);
    __syncthreads();
    const float* W2 = fw2 + (size_t)t * 128 * 128;
    float o[BPB];
#pragma unroll
    for (int bb = 0; bb < BPB; bb++) o[bb] = 0.f;
    for (int k = 0; k < 128; k++) {
        float w = W2[k * 128 + tid];
#pragma unroll
        for (int bb = 0; bb < BPB; bb++) o[bb] = fmaf(t1s[bb * 130 + k], w, o[bb]);
    }
    float b2 = fb2[t * 128 + tid];
#pragma unroll
    for (int bb = 0; bb < BPB; bb++) {
        int b = b0 + bb;
        if (b <= NBINS) {
            float d = (float)b * step;
            float C = 0.5f * (cosf(d * 0.62831853072f) + 1.0f);
            g_tableH[((size_t)t * (NBINS + 1) + b) * 128 + tid] = __float2half((o[bb] + b2) * C);
        }
    }
}

// ---- fp16 mma building blocks ----
template <int ROWS>
__device__ __forceinline__ void load_h16(uint32_t* dst, const __half* src, int tid) {
#pragma unroll
    for (int i = 0; i < ROWS * 16 / 256; i++) {
        int idx = tid + i * 256;
        int row = idx >> 4, q = idx & 15;
        uint4 v = *(const uint4*)&src[(size_t)row * 128 + q * 8];
        *(uint4*)&dst[row * ASTR + q * 4] = v;
    }
}
// fragment loads via ldmatrix (byte-identical registers to the scalar mapping)
template <int NT>
__device__ __forceinline__ void mma_tile(float acc[][NT][4], const uint32_t* As,
                                         const uint32_t* Bs, int wm, int wn, int lane) {
    uint32_t a_base = (uint32_t)__cvta_generic_to_shared(As);
    uint32_t b_base = (uint32_t)__cvta_generic_to_shared(Bs);
    int g = lane >> 3, rw = lane & 7;
    uint32_t aaddr[2];
#pragma unroll
    for (int mt = 0; mt < 2; mt++)
        aaddr[mt] = a_base +
            (uint32_t)((wm * 32 + mt * 16 + (g & 1) * 8 + rw) * (ASTR * 4) + (g >> 1) * 16);
    uint32_t baddr[NT / 2];
#pragma unroll
    for (int p = 0; p < NT / 2; p++)
        baddr[p] = b_base +
            (uint32_t)((wn * (NT * 8) + p * 16 + (g >> 1) * 8 + rw) * (ASTR * 4) + (g & 1) * 16);
#pragma unroll
    for (int ks = 0; ks < 8; ks++) {
        uint32_t af[2][4];
#pragma unroll
        for (int mt = 0; mt < 2; mt++)
            ldsm_x4(af[mt][0], af[mt][1], af[mt][2], af[mt][3], aaddr[mt] + ks * 32);
        uint32_t bf[NT][2];
#pragma unroll
        for (int p = 0; p < NT / 2; p++) {
            uint32_t r0, r1, r2, r3;
            ldsm_x4(r0, r1, r2, r3, baddr[p] + ks * 32);
            bf[2 * p][0] = r0; bf[2 * p][1] = r1;
            bf[2 * p + 1][0] = r2; bf[2 * p + 1][1] = r3;
        }
#pragma unroll
        for (int mt = 0; mt < 2; mt++)
#pragma unroll
            for (int nt = 0; nt < NT; nt++) mma_f16(acc[mt][nt], af[mt], bf[nt]);
    }
}

// h = r @ win[0]   (t=0 only; later h's fused into k_dr)
__global__ __launch_bounds__(256, 2) void k_mma_h(int t) {
    extern __shared__ uint32_t sm_u32[];
    uint32_t* As = sm_u32;
    uint32_t* Bs = sm_u32 + 128 * ASTR;
    int tid = threadIdx.x, lane = tid & 31, wid = tid >> 5, wm = wid & 3, wn = wid >> 2;
    load_h16<128>(As, g_rh + (size_t)blockIdx.x * 16384, tid);
    load_h16<128>(Bs, g_wH + (size_t)t * 16384, tid);
    __syncthreads();
    float acc[2][8][4] = {};
    mma_tile<8>(acc, As, Bs, wm, wn, lane);
    uint32_t* H = (uint32_t*)(g_h + (size_t)blockIdx.x * 16384);
#pragma unroll
    for (int mt = 0; mt < 2; mt++) {
        int r0 = wm * 32 + mt * 16 + (lane >> 2);
#pragma unroll
        for (int nt = 0; nt < 8; nt++) {
            int w = wn * 32 + nt * 4 + (lane & 3);
            H[r0 * 64 + w] = pack_h2(acc[mt][nt][0], acc[mt][nt][1]);
            H[(r0 + 8) * 64 + w] = pack_h2(acc[mt][nt][2], acc[mt][nt][3]);
        }
    }
}

// fused: r += ssp(y@W1+b1)@W2+b2 ; then LAST==0: h=r_new@win[t+1] ; LAST==1: head
template <int LAST>
__global__ __launch_bounds__(256, 2) void k_dr(int t, const float* __restrict__ b1,
                                               const float* __restrict__ b2,
                                               const float* __restrict__ ba1,
                                               const float* __restrict__ wa2,
                                               const float* __restrict__ ba2,
                                               const int* __restrict__ mol,
                                               float* __restrict__ out) {
    extern __shared__ uint32_t sm_u32[];
    uint32_t* As = sm_u32;
    uint32_t* Bs = sm_u32 + 128 * ASTR;
    float* sred = (float*)(sm_u32 + 2 * 128 * ASTR);   // 128 floats (LAST only)
    int tid = threadIdx.x, lane = tid & 31, wid = tid >> 5, wm = wid & 3, wn = wid >> 2;

    // GEMM1: U = ssp(y @ W1 + b1)
    load_h16<128>(As, g_y + (size_t)blockIdx.x * 16384, tid);
    load_h16<128>(Bs, g_wH + (size_t)(3 + t) * 16384, tid);
    __syncthreads();
    float acc[2][8][4] = {};
    mma_tile<8>(acc, As, Bs, wm, wn, lane);
    __syncthreads();
#pragma unroll
    for (int mt = 0; mt < 2; mt++) {
        int r0 = wm * 32 + mt * 16 + (lane >> 2);
#pragma unroll
        for (int nt = 0; nt < 8; nt++) {
            int col = wn * 64 + nt * 8 + (lane & 3) * 2;
            int w = wn * 32 + nt * 4 + (lane & 3);
            float bb0 = b1[col], bb1 = b1[col + 1];
            As[r0 * ASTR + w] = pack_h2(sspf(acc[mt][nt][0] + bb0), sspf(acc[mt][nt][1] + bb1));
            As[(r0 + 8) * ASTR + w] = pack_h2(sspf(acc[mt][nt][2] + bb0), sspf(acc[mt][nt][3] + bb1));
        }
    }
    load_h16<128>(Bs, g_wH + (size_t)(6 + t) * 16384, tid);
    __syncthreads();

    // GEMM2: dr = U @ W2 + b2 ; r_new = r + dr (fp16 stream), restage into As
    float acc2[2][8][4] = {};
    mma_tile<8>(acc2, As, Bs, wm, wn, lane);
    __syncthreads();
    uint32_t* RH = (uint32_t*)(g_rh + (size_t)blockIdx.x * 16384);
#pragma unroll
    for (int mt = 0; mt < 2; mt++) {
        int r0 = wm * 32 + mt * 16 + (lane >> 2);
#pragma unroll
        for (int nt = 0; nt < 8; nt++) {
            int col = wn * 64 + nt * 8 + (lane & 3) * 2;
            int w = wn * 32 + nt * 4 + (lane & 3);
            float bb0 = b2[col], bb1 = b2[col + 1];
#pragma unroll
            for (int half = 0; half < 2; half++) {
                int rr = r0 + half * 8;
                uint32_t old = RH[rr * 64 + w];
                float2 ro = __half22float2(*(__half2*)&old);
                float v0 = ro.x + acc2[mt][nt][half * 2]     + bb0;
                float v1 = ro.y + acc2[mt][nt][half * 2 + 1] + bb1;
                uint32_t pk = pack_h2(v0, v1);
                RH[rr * 64 + w] = pk;
                As[rr * ASTR + w] = pk;
            }
        }
    }

    if (LAST == 0) {
        // GEMM3: h = r_new @ win[t+1]
        load_h16<128>(Bs, g_wH + (size_t)(t + 1) * 16384, tid);
        __syncthreads();
        float acc3[2][8][4] = {};
        mma_tile<8>(acc3, As, Bs, wm, wn, lane);
        uint32_t* H = (uint32_t*)(g_h + (size_t)blockIdx.x * 16384);
#pragma unroll
        for (int mt = 0; mt < 2; mt++) {
            int r0 = wm * 32 + mt * 16 + (lane >> 2);
#pragma unroll
            for (int nt = 0; nt < 8; nt++) {
                int w = wn * 32 + nt * 4 + (lane & 3);
                H[r0 * 64 + w] = pack_h2(acc3[mt][nt][0], acc3[mt][nt][1]);
                H[(r0 + 8) * 64 + w] = pack_h2(acc3[mt][nt][2], acc3[mt][nt][3]);
            }
        }
    } else {
        // head: out[mol] += ssp(r_new @ wa1 + ba1) . wa2 + ba2
        load_h16<64>(Bs, g_wH + (size_t)9 * 16384, tid);
        if (tid < 128) sred[tid] = 0.f;
        __syncthreads();
        float acc3[2][4][4] = {};
        mma_tile<4>(acc3, As, Bs, wm, wn, lane);
#pragma unroll
        for (int mt = 0; mt < 2; mt++) {
            int r0 = wm * 32 + mt * 16 + (lane >> 2);
            float p0 = 0.f, p1 = 0.f;
#pragma unroll
            for (int nt = 0; nt < 4; nt++) {
                int col = wn * 32 + nt * 8 + (lane & 3) * 2;
                float bb0 = ba1[col], bb1 = ba1[col + 1];
                float w0 = wa2[col], w1 = wa2[col + 1];
                p0 += sspf(acc3[mt][nt][0] + bb0) * w0 + sspf(acc3[mt][nt][1] + bb1) * w1;
                p1 += sspf(acc3[mt][nt][2] + bb0) * w0 + sspf(acc3[mt][nt][3] + bb1) * w1;
            }
            atomicAdd(&sred[r0], p0);
            atomicAdd(&sred[r0 + 8], p1);
        }
        __syncthreads();
        if (tid < 128)
            atomicAdd(&out[mol[blockIdx.x * 128 + tid]], sred[tid] + ba2[0]);
    }
}

// y[i,:] = sum lerp(table,d) * h[other,:]; 1 warp per atom; fp16 table/h/y
__global__ __launch_bounds__(256) void k_agg(int t) {
    int gid = blockIdx.x * blockDim.x + threadIdx.x;
    int atom = gid >> 5, lane = gid & 31;
    const uint2* tabH = (const uint2*)(g_tableH + (size_t)t * (NBINS + 1) * 128);
    const uint2* h2 = (const uint2*)g_h;
    int s0 = g_start[atom], s1 = g_start[atom + 1];
    float4 acc = make_float4(0, 0, 0, 0);
    for (int s = s0; s < s1; s++) {
        int j = g_slot_other[s];
        float p = g_slot_pos[s];
        int b = (int)p;
        float f = p - (float)b;
        uint2 w0u = tabH[(size_t)b * 32 + lane];
        uint2 w1u = tabH[(size_t)(b + 1) * 32 + lane];
        uint2 hh = h2[(size_t)j * 32 + lane];
        float2 w0a = __half22float2(*(__half2*)&w0u.x);
        float2 w0b = __half22float2(*(__half2*)&w0u.y);
        float2 w1a = __half22float2(*(__half2*)&w1u.x);
        float2 w1b = __half22float2(*(__half2*)&w1u.y);
        float2 fa = __half22float2(*(__half2*)&hh.x);
        float2 fb = __half22float2(*(__half2*)&hh.y);
        acc.x = fmaf(fmaf(f, w1a.x - w0a.x, w0a.x), fa.x, acc.x);
        acc.y = fmaf(fmaf(f, w1a.y - w0a.y, w0a.y), fa.y, acc.y);
        acc.z = fmaf(fmaf(f, w1b.x - w0b.x, w0b.x), fb.x, acc.z);
        acc.w = fmaf(fmaf(f, w1b.y - w0b.y, w0b.y), fb.y, acc.w);
    }
    uint2 o;
    o.x = pack_h2(acc.x, acc.y);
    o.y = pack_h2(acc.z, acc.w);
    ((uint2*)g_y)[(size_t)atom * 32 + lane] = o;
}

extern "C" void kernel_launch(void* const* d_in, const int* in_sizes, int n_in,
                              void* d_out, int out_size) {
    const float* xyz   = (const float*)d_in[0];
    const float* emb   = (const float*)d_in[1];
    const float* fw1   = (const float*)d_in[2];
    const float* fb1   = (const float*)d_in[3];
    const float* fw2   = (const float*)d_in[4];
    const float* fb2   = (const float*)d_in[5];
    const float* win   = (const float*)d_in[6];
    const float* wout1 = (const float*)d_in[7];
    const float* bout1 = (const float*)d_in[8];
    const float* wout2 = (const float*)d_in[9];
    const float* bout2 = (const float*)d_in[10];
    const float* wa1   = (const float*)d_in[11];
    const float* ba1   = (const float*)d_in[12];
    const float* wa2   = (const float*)d_in[13];
    const float* ba2   = (const float*)d_in[14];
    const int*   z     = (const int*)d_in[15];
    const int*   a     = (const int*)d_in[16];
    const int*   mol   = (const int*)d_in[17];
    float* out = (float*)d_out;

    const int SM_BIG = (2 * 128 * ASTR + 128) * 4;   // 70144 -> 2 CTA/SM
    cudaFuncSetAttribute(k_mma_h, cudaFuncAttributeMaxDynamicSharedMemorySize, SM_BIG);
    cudaFuncSetAttribute(k_dr<0>, cudaFuncAttributeMaxDynamicSharedMemorySize, SM_BIG);
    cudaFuncSetAttribute(k_dr<1>, cudaFuncAttributeMaxDynamicSharedMemorySize, SM_BIG);

    // one-time side streams + events (host objects only; no device allocation)
    static cudaStream_t sA = nullptr, sB = nullptr;
    static cudaEvent_t ev0 = nullptr, evA = nullptr, evB = nullptr;
    if (!sA) {
        cudaStreamCreateWithFlags(&sA, cudaStreamNonBlocking);
        cudaStreamCreateWithFlags(&sB, cudaStreamNonBlocking);
        cudaEventCreateWithFlags(&ev0, cudaEventDisableTiming);
        cudaEventCreateWithFlags(&evA, cudaEventDisableTiming);
        cudaEventCreateWithFlags(&evB, cudaEventDisableTiming);
    }

    // fork from the (capturing) calling stream
    cudaEventRecord(ev0, 0);
    cudaStreamWaitEvent(sA, ev0, 0);
    cudaStreamWaitEvent(sB, ev0, 0);

    // branch B: edge/CSR/table prep chain
    k_prep<<<NA / 256, 256, 0, sB>>>(out);
    k_edge<<<NE / 256, 256, 0, sB>>>(xyz, a);
    k_scan1<<<512, 256, 0, sB>>>();
    k_scan2<<<1, 512, 0, sB>>>();
    k_scan3<<<512, 256, 0, sB>>>();
    k_fill<<<NE / 256, 256, 0, sB>>>(a);
    k_table<<<3 * 257, 128, 0, sB>>>(fw1, fb1, fw2, fb2);
    cudaEventRecord(evB, sB);

    // branch A: embeddings + weights + first h-GEMM
    k_embed<<<(NA * 32) / 256, 256, 0, sA>>>(emb, z);
    k_wconv<<<640, 256, 0, sA>>>(win, wout1, wout2, wa1);
    k_mma_h<<<NA / 128, 256, SM_BIG, sA>>>(0);

    // join B into A, then the t-loop on A
    cudaStreamWaitEvent(sA, evB, 0);
    for (int t = 0; t < 3; t++) {
        k_agg<<<(NA * 32) / 256, 256, 0, sA>>>(t);
        if (t < 2)
            k_dr<0><<<NA / 128, 256, SM_BIG, sA>>>(t, bout1 + t * 128, bout2 + t * 128,
                                                   ba1, wa2, ba2, mol, out);
        else
            k_dr<1><<<NA / 128, 256, SM_BIG, sA>>>(t, bout1 + t * 128, bout2 + t * 128,
                                                   ba1, wa2, ba2, mol, out);
    }
    cudaEventRecord(evA, sA);
    cudaStreamWaitEvent(0, evA, 0);
}

// round 14
// speedup vs baseline: 1.8476x; 1.0043x over previous
#include <cuda_runtime.h>
#include <cuda_fp16.h>
#include <stdint.h>

#define NA 131072
#define NE 524288
#define NM 2048
#define GG 50
#define NBINS 4096
#define DCUT 6.0f
#define LN2F 0.69314718056f
#define ASTR 68  // u32 words per smem row (64 data + 4 pad); 68 % 32 == 4 -> conflict-free

// ---- device scratch ----
__device__ __half g_rh[NA * 128];   // fp16 residual stream r
__device__ __half g_h[NA * 128];
__device__ __half g_y[NA * 128];
__device__ __half g_wH[10 * 128 * 128];  // transposed fp16 weights [m][n][k]
__device__ __half g_tableH[3 * (NBINS + 1) * 128];
__device__ __half g_tabP[3 * NBINS * 256];  // paired rows {W(b), W(b+1)} per lane
__device__ float g_edge_d[NE];
__device__ int   g_deg[NA];
__device__ int   g_start[NA + 1];
__device__ int   g_cur[NA];
__device__ int   g_bsum[512];
__device__ int   g_slot_other[2 * NE];
__device__ float g_slot_pos[2 * NE];

__device__ __forceinline__ float sspf(float x) {
    return fmaxf(x, 0.f) + log1pf(__expf(-fabsf(x))) - LN2F;
}
__device__ __forceinline__ uint32_t pack_h2(float a, float b) {
    __half2 p = __floats2half2_rn(a, b);
    return *(uint32_t*)&p;
}
__device__ __forceinline__ void mma_f16(float* c, const uint32_t* a, const uint32_t* b) {
    asm volatile(
        "mma.sync.aligned.m16n8k16.row.col.f32.f16.f16.f32 "
        "{%0,%1,%2,%3}, {%4,%5,%6,%7}, {%8,%9}, {%0,%1,%2,%3};"
        : "+f"(c[0]), "+f"(c[1]), "+f"(c[2]), "+f"(c[3])
        : "r"(a[0]), "r"(a[1]), "r"(a[2]), "r"(a[3]), "r"(b[0]), "r"(b[1]));
}
__device__ __forceinline__ void ldsm_x4(uint32_t& r0, uint32_t& r1, uint32_t& r2,
                                        uint32_t& r3, uint32_t addr) {
    asm volatile("ldmatrix.sync.aligned.m8n8.x4.shared.b16 {%0,%1,%2,%3}, [%4];"
                 : "=r"(r0), "=r"(r1), "=r"(r2), "=r"(r3) : "r"(addr));
}

// ---- prep kernels ----
__global__ void k_prep(float* __restrict__ out) {
    int i = blockIdx.x * blockDim.x + threadIdx.x;
    if (i < NA) g_deg[i] = 0;
    if (i < NM) out[i] = 0.f;
}
__global__ void k_embed(const float* __restrict__ emb, const int* __restrict__ z) {
    int idx = blockIdx.x * blockDim.x + threadIdx.x;
    int atom = idx >> 5, q = idx & 31;
    float4 v = ((const float4*)emb)[(size_t)z[atom] * 32 + q];
    uint2 o;
    o.x = pack_h2(v.x, v.y);
    o.y = pack_h2(v.z, v.w);
    ((uint2*)g_rh)[(size_t)atom * 32 + q] = o;
}
__global__ void k_edge(const float* __restrict__ xyz, const int* __restrict__ a) {
    int e = blockIdx.x * blockDim.x + threadIdx.x;
    if (e >= NE) return;
    int i = a[2 * e], j = a[2 * e + 1];
    float dx = xyz[3 * i] - xyz[3 * j];
    float dy = xyz[3 * i + 1] - xyz[3 * j + 1];
    float dz = xyz[3 * i + 2] - xyz[3 * j + 2];
    float d = sqrtf(dx * dx + dy * dy + dz * dz);
    g_edge_d[e] = d;
    if (d < DCUT) { atomicAdd(&g_deg[i], 1); atomicAdd(&g_deg[j], 1); }
}
__global__ void k_scan1() {
    int b = blockIdx.x, t = threadIdx.x, i = b * 256 + t;
    int lane = t & 31, w = t >> 5;
    int v = g_deg[i], s = v;
#pragma unroll
    for (int off = 1; off < 32; off <<= 1) {
        int u = __shfl_up_sync(0xffffffffu, s, off);
        if (lane >= off) s += u;
    }
    __shared__ int wsum[8];
    if (lane == 31) wsum[w] = s;
    __syncthreads();
    if (t < 8) {
        int x = wsum[t];
#pragma unroll
        for (int off = 1; off < 8; off <<= 1) {
            int u = __shfl_up_sync(0xffu, x, off);
            if (t >= off) x += u;
        }
        wsum[t] = x;
    }
    __syncthreads();
    int base = (w > 0) ? wsum[w - 1] : 0;
    g_start[i] = base + s - v;
    if (t == 255) g_bsum[b] = wsum[7];
}
__global__ void k_scan2() {
    __shared__ int sh[512];
    int t = threadIdx.x;
    int v = g_bsum[t];
    sh[t] = v;
    __syncthreads();
    for (int off = 1; off < 512; off <<= 1) {
        int u = (t >= off) ? sh[t - off] : 0;
        __syncthreads();
        sh[t] += u;
        __syncthreads();
    }
    g_bsum[t] = sh[t] - v;
    if (t == 511) g_start[NA] = sh[511];
}
__global__ void k_scan3() {
    int b = blockIdx.x, i = b * 256 + threadIdx.x;
    int s = g_start[i] + g_bsum[b];
    g_start[i] = s;
    g_cur[i] = s;
}
__global__ void k_fill(const int* __restrict__ a) {
    int e = blockIdx.x * blockDim.x + threadIdx.x;
    if (e >= NE) return;
    float d = g_edge_d[e];
    if (d >= DCUT) return;
    int i = a[2 * e], j = a[2 * e + 1];
    float p = d * ((float)NBINS / DCUT);
    int s0 = atomicAdd(&g_cur[i], 1);
    g_slot_other[s0] = j; g_slot_pos[s0] = p;
    int s1 = atomicAdd(&g_cur[j], 1);
    g_slot_other[s1] = i; g_slot_pos[s1] = p;
}

// transpose + fp16 weights: g_wH[m][n*128+k]
__global__ void k_wconv(const float* __restrict__ win, const float* __restrict__ wout1,
                        const float* __restrict__ wout2, const float* __restrict__ wa1) {
    int idx = blockIdx.x * blockDim.x + threadIdx.x;
    int m = idx >> 14, pos = idx & 16383;
    if (m < 9) {
        int n = pos >> 7, k = pos & 127;
        const float* src = (m < 3) ? win + (size_t)m * 16384
                         : (m < 6) ? wout1 + (size_t)(m - 3) * 16384
                                   : wout2 + (size_t)(m - 6) * 16384;
        g_wH[idx] = __float2half(src[k * 128 + n]);
    } else if (m == 9 && pos < 8192) {
        int n = pos >> 7, k = pos & 127;
        g_wH[(size_t)9 * 16384 + pos] = __float2half(wa1[k * 64 + n]);
    }
}

// W(d)*C(d) table (fp16 storage)
__global__ __launch_bounds__(128) void k_table(const float* __restrict__ fw1,
                                               const float* __restrict__ fb1,
                                               const float* __restrict__ fw2,
                                               const float* __restrict__ fb2) {
    const int BPB = 16;
    int chunk = blockIdx.x % 257, t = blockIdx.x / 257;
    int b0 = chunk * BPB, tid = threadIdx.x;
    __shared__ float gsh[BPB * 52];
    __shared__ float t1s[BPB * 130];
    const float step = DCUT / (float)NBINS;
    const float wth = 5.0f / 49.0f;
    const float coef = -0.5f / (wth * wth);
    for (int i = tid; i < BPB * GG; i += 128) {
        int bb = i / GG, k = i % GG;
        float d = (float)(b0 + bb) * step;
        float x = d - 5.0f * (float)k / 49.0f;
        gsh[bb * 52 + k] = __expf(coef * x * x);
    }
    __syncthreads();
    const float* W1 = fw1 + (size_t)t * GG * 128;
    float s[BPB];
#pragma unroll
    for (int bb = 0; bb < BPB; bb++) s[bb] = 0.f;
    for (int k = 0; k < GG; k++) {
        float w = W1[k * 128 + tid];
#pragma unroll
        for (int bb = 0; bb < BPB; bb++) s[bb] = fmaf(gsh[bb * 52 + k], w, s[bb]);
    }
    float b1 = fb1[t * 128 + tid];
#pragma unroll
    for (int bb = 0; bb < BPB; bb++) t1s[bb * 130 + tid] = sspf(s[bb] + b1);
    __syncthreads();
    const float* W2 = fw2 + (size_t)t * 128 * 128;
    float o[BPB];
#pragma unroll
    for (int bb = 0; bb < BPB; bb++) o[bb] = 0.f;
    for (int k = 0; k < 128; k++) {
        float w = W2[k * 128 + tid];
#pragma unroll
        for (int bb = 0; bb < BPB; bb++) o[bb] = fmaf(t1s[bb * 130 + k], w, o[bb]);
    }
    float b2 = fb2[t * 128 + tid];
#pragma unroll
    for (int bb = 0; bb < BPB; bb++) {
        int b = b0 + bb;
        if (b <= NBINS) {
            float d = (float)b * step;
            float C = 0.5f * (cosf(d * 0.62831853072f) + 1.0f);
            g_tableH[((size_t)t * (NBINS + 1) + b) * 128 + tid] = __float2half((o[bb] + b2) * C);
        }
    }
}

// build paired table: tabP[t][b][lane] = {W(b)[4], W(b+1)[4]} as uint4
__global__ void k_pair() {
    int idx = blockIdx.x * blockDim.x + threadIdx.x;  // 3*4096*32
    int lane = idx & 31;
    int b = (idx >> 5) & (NBINS - 1);
    int t = idx >> 17;
    const uint2* src = (const uint2*)(g_tableH + (size_t)t * (NBINS + 1) * 128);
    uint2 w0 = src[(size_t)b * 32 + lane];
    uint2 w1 = src[(size_t)(b + 1) * 32 + lane];
    uint4 o;
    o.x = w0.x; o.y = w0.y; o.z = w1.x; o.w = w1.y;
    ((uint4*)g_tabP)[(size_t)(t * NBINS + b) * 32 + lane] = o;
}

// ---- fp16 mma building blocks ----
template <int ROWS>
__device__ __forceinline__ void load_h16(uint32_t* dst, const __half* src, int tid) {
#pragma unroll
    for (int i = 0; i < ROWS * 16 / 256; i++) {
        int idx = tid + i * 256;
        int row = idx >> 4, q = idx & 15;
        uint4 v = *(const uint4*)&src[(size_t)row * 128 + q * 8];
        *(uint4*)&dst[row * ASTR + q * 4] = v;
    }
}
template <int NT>
__device__ __forceinline__ void mma_tile(float acc[][NT][4], const uint32_t* As,
                                         const uint32_t* Bs, int wm, int wn, int lane) {
    uint32_t a_base = (uint32_t)__cvta_generic_to_shared(As);
    uint32_t b_base = (uint32_t)__cvta_generic_to_shared(Bs);
    int g = lane >> 3, rw = lane & 7;
    uint32_t aaddr[2];
#pragma unroll
    for (int mt = 0; mt < 2; mt++)
        aaddr[mt] = a_base +
            (uint32_t)((wm * 32 + mt * 16 + (g & 1) * 8 + rw) * (ASTR * 4) + (g >> 1) * 16);
    uint32_t baddr[NT / 2];
#pragma unroll
    for (int p = 0; p < NT / 2; p++)
        baddr[p] = b_base +
            (uint32_t)((wn * (NT * 8) + p * 16 + (g >> 1) * 8 + rw) * (ASTR * 4) + (g & 1) * 16);
#pragma unroll
    for (int ks = 0; ks < 8; ks++) {
        uint32_t af[2][4];
#pragma unroll
        for (int mt = 0; mt < 2; mt++)
            ldsm_x4(af[mt][0], af[mt][1], af[mt][2], af[mt][3], aaddr[mt] + ks * 32);
        uint32_t bf[NT][2];
#pragma unroll
        for (int p = 0; p < NT / 2; p++) {
            uint32_t r0, r1, r2, r3;
            ldsm_x4(r0, r1, r2, r3, baddr[p] + ks * 32);
            bf[2 * p][0] = r0; bf[2 * p][1] = r1;
            bf[2 * p + 1][0] = r2; bf[2 * p + 1][1] = r3;
        }
#pragma unroll
        for (int mt = 0; mt < 2; mt++)
#pragma unroll
            for (int nt = 0; nt < NT; nt++) mma_f16(acc[mt][nt], af[mt], bf[nt]);
    }
}

// h = r @ win[0]   (t=0 only; later h's fused into k_dr)
__global__ __launch_bounds__(256, 2) void k_mma_h(int t) {
    extern __shared__ uint32_t sm_u32[];
    uint32_t* As = sm_u32;
    uint32_t* Bs = sm_u32 + 128 * ASTR;
    int tid = threadIdx.x, lane = tid & 31, wid = tid >> 5, wm = wid & 3, wn = wid >> 2;
    load_h16<128>(As, g_rh + (size_t)blockIdx.x * 16384, tid);
    load_h16<128>(Bs, g_wH + (size_t)t * 16384, tid);
    __syncthreads();
    float acc[2][8][4] = {};
    mma_tile<8>(acc, As, Bs, wm, wn, lane);
    uint32_t* H = (uint32_t*)(g_h + (size_t)blockIdx.x * 16384);
#pragma unroll
    for (int mt = 0; mt < 2; mt++) {
        int r0 = wm * 32 + mt * 16 + (lane >> 2);
#pragma unroll
        for (int nt = 0; nt < 8; nt++) {
            int w = wn * 32 + nt * 4 + (lane & 3);
            H[r0 * 64 + w] = pack_h2(acc[mt][nt][0], acc[mt][nt][1]);
            H[(r0 + 8) * 64 + w] = pack_h2(acc[mt][nt][2], acc[mt][nt][3]);
        }
    }
}

// fused: r += ssp(y@W1+b1)@W2+b2 ; then LAST==0: h=r_new@win[t+1] ; LAST==1: head
template <int LAST>
__global__ __launch_bounds__(256, 2) void k_dr(int t, const float* __restrict__ b1,
                                               const float* __restrict__ b2,
                                               const float* __restrict__ ba1,
                                               const float* __restrict__ wa2,
                                               const float* __restrict__ ba2,
                                               const int* __restrict__ mol,
                                               float* __restrict__ out) {
    extern __shared__ uint32_t sm_u32[];
    uint32_t* As = sm_u32;
    uint32_t* Bs = sm_u32 + 128 * ASTR;
    float* sred = (float*)(sm_u32 + 2 * 128 * ASTR);
    int tid = threadIdx.x, lane = tid & 31, wid = tid >> 5, wm = wid & 3, wn = wid >> 2;

    load_h16<128>(As, g_y + (size_t)blockIdx.x * 16384, tid);
    load_h16<128>(Bs, g_wH + (size_t)(3 + t) * 16384, tid);
    __syncthreads();
    float acc[2][8][4] = {};
    mma_tile<8>(acc, As, Bs, wm, wn, lane);
    __syncthreads();
#pragma unroll
    for (int mt = 0; mt < 2; mt++) {
        int r0 = wm * 32 + mt * 16 + (lane >> 2);
#pragma unroll
        for (int nt = 0; nt < 8; nt++) {
            int col = wn * 64 + nt * 8 + (lane & 3) * 2;
            int w = wn * 32 + nt * 4 + (lane & 3);
            float bb0 = b1[col], bb1 = b1[col + 1];
            As[r0 * ASTR + w] = pack_h2(sspf(acc[mt][nt][0] + bb0), sspf(acc[mt][nt][1] + bb1));
            As[(r0 + 8) * ASTR + w] = pack_h2(sspf(acc[mt][nt][2] + bb0), sspf(acc[mt][nt][3] + bb1));
        }
    }
    load_h16<128>(Bs, g_wH + (size_t)(6 + t) * 16384, tid);
    __syncthreads();

    float acc2[2][8][4] = {};
    mma_tile<8>(acc2, As, Bs, wm, wn, lane);
    __syncthreads();
    uint32_t* RH = (uint32_t*)(g_rh + (size_t)blockIdx.x * 16384);
#pragma unroll
    for (int mt = 0; mt < 2; mt++) {
        int r0 = wm * 32 + mt * 16 + (lane >> 2);
#pragma unroll
        for (int nt = 0; nt < 8; nt++) {
            int col = wn * 64 + nt * 8 + (lane & 3) * 2;
            int w = wn * 32 + nt * 4 + (lane & 3);
            float bb0 = b2[col], bb1 = b2[col + 1];
#pragma unroll
            for (int half = 0; half < 2; half++) {
                int rr = r0 + half * 8;
                uint32_t old = RH[rr * 64 + w];
                float2 ro = __half22float2(*(__half2*)&old);
                float v0 = ro.x + acc2[mt][nt][half * 2]     + bb0;
                float v1 = ro.y + acc2[mt][nt][half * 2 + 1] + bb1;
                uint32_t pk = pack_h2(v0, v1);
                RH[rr * 64 + w] = pk;
                As[rr * ASTR + w] = pk;
            }
        }
    }

    if (LAST == 0) {
        load_h16<128>(Bs, g_wH + (size_t)(t + 1) * 16384, tid);
        __syncthreads();
        float acc3[2][8][4] = {};
        mma_tile<8>(acc3, As, Bs, wm, wn, lane);
        uint32_t* H = (uint32_t*)(g_h + (size_t)blockIdx.x * 16384);
#pragma unroll
        for (int mt = 0; mt < 2; mt++) {
            int r0 = wm * 32 + mt * 16 + (lane >> 2);
#pragma unroll
            for (int nt = 0; nt < 8; nt++) {
                int w = wn * 32 + nt * 4 + (lane & 3);
                H[r0 * 64 + w] = pack_h2(acc3[mt][nt][0], acc3[mt][nt][1]);
                H[(r0 + 8) * 64 + w] = pack_h2(acc3[mt][nt][2], acc3[mt][nt][3]);
            }
        }
    } else {
        load_h16<64>(Bs, g_wH + (size_t)9 * 16384, tid);
        if (tid < 128) sred[tid] = 0.f;
        __syncthreads();
        float acc3[2][4][4] = {};
        mma_tile<4>(acc3, As, Bs, wm, wn, lane);
#pragma unroll
        for (int mt = 0; mt < 2; mt++) {
            int r0 = wm * 32 + mt * 16 + (lane >> 2);
            float p0 = 0.f, p1 = 0.f;
#pragma unroll
            for (int nt = 0; nt < 4; nt++) {
                int col = wn * 32 + nt * 8 + (lane & 3) * 2;
                float bb0 = ba1[col], bb1 = ba1[col + 1];
                float w0 = wa2[col], w1 = wa2[col + 1];
                p0 += sspf(acc3[mt][nt][0] + bb0) * w0 + sspf(acc3[mt][nt][1] + bb1) * w1;
                p1 += sspf(acc3[mt][nt][2] + bb0) * w0 + sspf(acc3[mt][nt][3] + bb1) * w1;
            }
            atomicAdd(&sred[r0], p0);
            atomicAdd(&sred[r0 + 8], p1);
        }
        __syncthreads();
        if (tid < 128)
            atomicAdd(&out[mol[blockIdx.x * 128 + tid]], sred[tid] + ba2[0]);
    }
}

// ---- aggregation: paired table + 2-way unrolled gather ----
__device__ __forceinline__ void agg_step(float4& A, uint4 tw, uint2 hh, float f) {
    float2 w0a = __half22float2(*(__half2*)&tw.x);
    float2 w0b = __half22float2(*(__half2*)&tw.y);
    float2 w1a = __half22float2(*(__half2*)&tw.z);
    float2 w1b = __half22float2(*(__half2*)&tw.w);
    float2 fa = __half22float2(*(__half2*)&hh.x);
    float2 fb = __half22float2(*(__half2*)&hh.y);
    A.x = fmaf(fmaf(f, w1a.x - w0a.x, w0a.x), fa.x, A.x);
    A.y = fmaf(fmaf(f, w1a.y - w0a.y, w0a.y), fa.y, A.y);
    A.z = fmaf(fmaf(f, w1b.x - w0b.x, w0b.x), fb.x, A.z);
    A.w = fmaf(fmaf(f, w1b.y - w0b.y, w0b.y), fb.y, A.w);
}
__global__ __launch_bounds__(256) void k_agg(int t) {
    int gid = blockIdx.x * blockDim.x + threadIdx.x;
    int atom = gid >> 5, lane = gid & 31;
    const uint4* tabP = ((const uint4*)g_tabP) + (size_t)t * NBINS * 32;
    const uint2* h2 = (const uint2*)g_h;
    int s0 = g_start[atom], s1 = g_start[atom + 1];
    float4 A0 = make_float4(0, 0, 0, 0), A1 = make_float4(0, 0, 0, 0);
    int s = s0;
    for (; s + 1 < s1; s += 2) {
        int ja = g_slot_other[s], jb = g_slot_other[s + 1];
        float pa = g_slot_pos[s], pb = g_slot_pos[s + 1];
        int ba = (int)pa, bb = (int)pb;
        float fa = pa - (float)ba, fb = pb - (float)bb;
        uint4 twa = tabP[(size_t)ba * 32 + lane];
        uint4 twb = tabP[(size_t)bb * 32 + lane];
        uint2 ha = h2[(size_t)ja * 32 + lane];
        uint2 hb = h2[(size_t)jb * 32 + lane];
        agg_step(A0, twa, ha, fa);
        agg_step(A1, twb, hb, fb);
    }
    if (s < s1) {
        int ja = g_slot_other[s];
        float pa = g_slot_pos[s];
        int ba = (int)pa;
        float fa = pa - (float)ba;
        uint4 twa = tabP[(size_t)ba * 32 + lane];
        uint2 ha = h2[(size_t)ja * 32 + lane];
        agg_step(A0, twa, ha, fa);
    }
    uint2 o;
    o.x = pack_h2(A0.x + A1.x, A0.y + A1.y);
    o.y = pack_h2(A0.z + A1.z, A0.w + A1.w);
    ((uint2*)g_y)[(size_t)atom * 32 + lane] = o;
}

extern "C" void kernel_launch(void* const* d_in, const int* in_sizes, int n_in,
                              void* d_out, int out_size) {
    const float* xyz   = (const float*)d_in[0];
    const float* emb   = (const float*)d_in[1];
    const float* fw1   = (const float*)d_in[2];
    const float* fb1   = (const float*)d_in[3];
    const float* fw2   = (const float*)d_in[4];
    const float* fb2   = (const float*)d_in[5];
    const float* win   = (const float*)d_in[6];
    const float* wout1 = (const float*)d_in[7];
    const float* bout1 = (const float*)d_in[8];
    const float* wout2 = (const float*)d_in[9];
    const float* bout2 = (const float*)d_in[10];
    const float* wa1   = (const float*)d_in[11];
    const float* ba1   = (const float*)d_in[12];
    const float* wa2   = (const float*)d_in[13];
    const float* ba2   = (const float*)d_in[14];
    const int*   z     = (const int*)d_in[15];
    const int*   a     = (const int*)d_in[16];
    const int*   mol   = (const int*)d_in[17];
    float* out = (float*)d_out;

    const int SM_BIG = (2 * 128 * ASTR + 128) * 4;   // 70144 -> 2 CTA/SM
    cudaFuncSetAttribute(k_mma_h, cudaFuncAttributeMaxDynamicSharedMemorySize, SM_BIG);
    cudaFuncSetAttribute(k_dr<0>, cudaFuncAttributeMaxDynamicSharedMemorySize, SM_BIG);
    cudaFuncSetAttribute(k_dr<1>, cudaFuncAttributeMaxDynamicSharedMemorySize, SM_BIG);

    static cudaStream_t sA = nullptr, sB = nullptr;
    static cudaEvent_t ev0 = nullptr, evA = nullptr, evB = nullptr;
    if (!sA) {
        cudaStreamCreateWithFlags(&sA, cudaStreamNonBlocking);
        cudaStreamCreateWithFlags(&sB, cudaStreamNonBlocking);
        cudaEventCreateWithFlags(&ev0, cudaEventDisableTiming);
        cudaEventCreateWithFlags(&evA, cudaEventDisableTiming);
        cudaEventCreateWithFlags(&evB, cudaEventDisableTiming);
    }

    cudaEventRecord(ev0, 0);
    cudaStreamWaitEvent(sA, ev0, 0);
    cudaStreamWaitEvent(sB, ev0, 0);

    // branch B: edge/CSR/table prep chain (+ paired table)
    k_prep<<<NA / 256, 256, 0, sB>>>(out);
    k_edge<<<NE / 256, 256, 0, sB>>>(xyz, a);
    k_scan1<<<512, 256, 0, sB>>>();
    k_scan2<<<1, 512, 0, sB>>>();
    k_scan3<<<512, 256, 0, sB>>>();
    k_fill<<<NE / 256, 256, 0, sB>>>(a);
    k_table<<<3 * 257, 128, 0, sB>>>(fw1, fb1, fw2, fb2);
    k_pair<<<(3 * NBINS * 32) / 256, 256, 0, sB>>>();
    cudaEventRecord(evB, sB);

    // branch A: embeddings + weights + first h-GEMM
    k_embed<<<(NA * 32) / 256, 256, 0, sA>>>(emb, z);
    k_wconv<<<640, 256, 0, sA>>>(win, wout1, wout2, wa1);
    k_mma_h<<<NA / 128, 256, SM_BIG, sA>>>(0);

    cudaStreamWaitEvent(sA, evB, 0);
    for (int t = 0; t < 3; t++) {
        k_agg<<<(NA * 32) / 256, 256, 0, sA>>>(t);
        if (t < 2)
            k_dr<0><<<NA / 128, 256, SM_BIG, sA>>>(t, bout1 + t * 128, bout2 + t * 128,
                                                   ba1, wa2, ba2, mol, out);
        else
            k_dr<1><<<NA / 128, 256, SM_BIG, sA>>>(t, bout1 + t * 128, bout2 + t * 128,
                                                   ba1, wa2, ba2, mol, out);
    }
    cudaEventRecord(evA, sA);
    cudaStreamWaitEvent(0, evA, 0);
}